// round 4
// baseline (speedup 1.0000x reference)
#include <cuda_runtime.h>
#include <cuda_bf16.h>
#include <math.h>

#define NN 50000
#define EE 800000
#define DD 128
#define BN_EPS 1e-5f

// ---------------- device scratch (no allocations allowed) ----------------
__device__ float g_h[(size_t)NN * DD];    // post-GEMM activations
__device__ float g_agg[(size_t)NN * DD];  // aggregated
__device__ float g_x2[(size_t)NN * DD];   // post BN+ReLU
__device__ int   g_deg[NN];
__device__ float g_dinv[NN];
__device__ int   g_rowptr[NN + 1];
__device__ int   g_rowcur[NN];
__device__ int   g_col[EE];
__device__ float g_sum[DD];
__device__ float g_sumsq[DD];
__device__ float g_scale[DD];
__device__ float g_shift[DD];
__device__ int   g_is64;

// ---------------- edge index access (int32 vs int64 tolerant) -----------
__global__ void detect_dtype_kernel(const int* __restrict__ ei) {
    if (threadIdx.x == 0 && blockIdx.x == 0) {
        // If underlying data is int64 (values < 2^31), every odd int32 slot
        // of the first few elements is 0. With real int32 data those slots
        // are random node ids in [0, 50000): P(all zero) ~ (2e-5)^8 ~ 0.
        int is64 = 1;
        #pragma unroll
        for (int i = 1; i < 16; i += 2)
            if (ei[i] != 0) is64 = 0;
        g_is64 = is64;
    }
}

__device__ __forceinline__ int edge_src(const int* ei, int e) {
    return g_is64 ? ei[2 * e] : ei[e];
}
__device__ __forceinline__ int edge_dst(const int* ei, int e) {
    return g_is64 ? ei[2 * (EE + e)] : ei[EE + e];
}

// ---------------- graph preprocessing ----------------
__global__ void zero_deg_kernel() {
    int i = blockIdx.x * blockDim.x + threadIdx.x;
    if (i < NN) g_deg[i] = 0;
}

__global__ void deg_count_kernel(const int* __restrict__ ei) {
    int e = blockIdx.x * blockDim.x + threadIdx.x;
    if (e < EE) atomicAdd(&g_deg[edge_dst(ei, e)], 1);
}

__global__ void scan_kernel() {
    // single block, 1024 threads: chunked exclusive scan of g_deg -> g_rowptr
    __shared__ int partial[1024];
    int tid = threadIdx.x;
    const int CH = (NN + 1023) / 1024;  // 49
    int base = tid * CH;
    int s = 0;
    for (int i = 0; i < CH; i++) {
        int idx = base + i;
        if (idx < NN) s += g_deg[idx];
    }
    partial[tid] = s;
    __syncthreads();
    // Hillis-Steele inclusive scan
    for (int off = 1; off < 1024; off <<= 1) {
        int v = 0;
        if (tid >= off) v = partial[tid - off];
        __syncthreads();
        if (tid >= off) partial[tid] += v;
        __syncthreads();
    }
    if (tid == 0) g_rowptr[NN] = partial[1023];
    int run = (tid == 0) ? 0 : partial[tid - 1];
    for (int i = 0; i < CH; i++) {
        int idx = base + i;
        if (idx < NN) {
            g_rowptr[idx] = run;
            g_rowcur[idx] = run;
            run += g_deg[idx];
        }
    }
}

__global__ void dinv_kernel() {
    int i = blockIdx.x * blockDim.x + threadIdx.x;
    if (i < NN) g_dinv[i] = rsqrtf((float)g_deg[i] + 1.0f);  // +1 self loop
}

__global__ void fill_kernel(const int* __restrict__ ei) {
    int e = blockIdx.x * blockDim.x + threadIdx.x;
    if (e < EE) {
        int d = edge_dst(ei, e);
        int s = edge_src(ei, e);
        int pos = atomicAdd(&g_rowcur[d], 1);
        g_col[pos] = s;
    }
}

// ---------------- SGEMM: C[M,128] = A[M,128] @ W[128,128] ----------------
// 64x128 block tile, BK=32, 256 threads, 4x8 register tile per thread.
__global__ __launch_bounds__(256) void gemm_kernel(
    const float* __restrict__ A, const float* __restrict__ W,
    float* __restrict__ C, int M)
{
    __shared__ float As[32][68];   // [k][m], padded for alignment/banks
    __shared__ float Ws[32][128];  // [k][n]

    int tid = threadIdx.x;
    int tx = tid & 15;    // col group (8 cols)
    int ty = tid >> 4;    // row group (4 rows)
    int m0 = blockIdx.x * 64;

    float acc[4][8];
    #pragma unroll
    for (int r = 0; r < 4; r++)
        #pragma unroll
        for (int c = 0; c < 8; c++) acc[r][c] = 0.0f;

    for (int k0 = 0; k0 < DD; k0 += 32) {
        // load A chunk (64x32) transposed into smem
        for (int j = tid; j < 512; j += 256) {
            int row = j >> 3;
            int kq = (j & 7) * 4;
            float4 v = make_float4(0.f, 0.f, 0.f, 0.f);
            if (m0 + row < M)
                v = *(const float4*)(A + (size_t)(m0 + row) * DD + k0 + kq);
            As[kq + 0][row] = v.x;
            As[kq + 1][row] = v.y;
            As[kq + 2][row] = v.z;
            As[kq + 3][row] = v.w;
        }
        // load W chunk (32x128)
        for (int j = tid; j < 1024; j += 256) {
            int kk = j >> 5;
            int nq = (j & 31) * 4;
            *(float4*)(&Ws[kk][nq]) =
                *(const float4*)(W + (size_t)(k0 + kk) * DD + nq);
        }
        __syncthreads();

        #pragma unroll
        for (int k = 0; k < 32; k++) {
            float4 a  = *(const float4*)(&As[k][ty * 4]);
            float4 w0 = *(const float4*)(&Ws[k][tx * 8]);
            float4 w1 = *(const float4*)(&Ws[k][tx * 8 + 4]);
            float av[4] = {a.x, a.y, a.z, a.w};
            float wv[8] = {w0.x, w0.y, w0.z, w0.w, w1.x, w1.y, w1.z, w1.w};
            #pragma unroll
            for (int r = 0; r < 4; r++)
                #pragma unroll
                for (int c = 0; c < 8; c++)
                    acc[r][c] = fmaf(av[r], wv[c], acc[r][c]);
        }
        __syncthreads();
    }

    #pragma unroll
    for (int r = 0; r < 4; r++) {
        int row = m0 + ty * 4 + r;
        if (row < M) {
            float4 o0 = make_float4(acc[r][0], acc[r][1], acc[r][2], acc[r][3]);
            float4 o1 = make_float4(acc[r][4], acc[r][5], acc[r][6], acc[r][7]);
            *(float4*)(C + (size_t)row * DD + tx * 8)     = o0;
            *(float4*)(C + (size_t)row * DD + tx * 8 + 4) = o1;
        }
    }
}

// ---------------- aggregation: agg[i] = sum_{e: dst=i} norm_e * h[src_e] + dinv_i^2 * h[i]
// one warp per node, lane owns 4 features (float4). CSR gather, no atomics.
__global__ __launch_bounds__(256) void agg_kernel(
    const float* __restrict__ h, float* __restrict__ out)
{
    int gw = (blockIdx.x * blockDim.x + threadIdx.x) >> 5;
    int lane = threadIdx.x & 31;
    if (gw >= NN) return;

    float di = g_dinv[gw];
    float4 acc = *(const float4*)(h + (size_t)gw * DD + lane * 4);
    float wself = di * di;
    acc.x *= wself; acc.y *= wself; acc.z *= wself; acc.w *= wself;

    int beg = g_rowptr[gw];
    int end = g_rowptr[gw + 1];
    for (int e = beg; e < end; e++) {
        int s = g_col[e];
        float w = g_dinv[s] * di;
        float4 v = *(const float4*)(h + (size_t)s * DD + lane * 4);
        acc.x = fmaf(v.x, w, acc.x);
        acc.y = fmaf(v.y, w, acc.y);
        acc.z = fmaf(v.z, w, acc.z);
        acc.w = fmaf(v.w, w, acc.w);
    }
    *(float4*)(out + (size_t)gw * DD + lane * 4) = acc;
}

// ---------------- BatchNorm ----------------
__global__ void zero_stats_kernel() {
    int f = threadIdx.x;
    if (f < DD) { g_sum[f] = 0.0f; g_sumsq[f] = 0.0f; }
}

__global__ __launch_bounds__(128) void stats_kernel(const float* __restrict__ a) {
    int f = threadIdx.x;  // 128 threads = one feature each
    float s = 0.0f, s2 = 0.0f;
    for (int n = blockIdx.x; n < NN; n += gridDim.x) {
        float v = a[(size_t)n * DD + f];
        s += v;
        s2 += v * v;
    }
    atomicAdd(&g_sum[f], s);
    atomicAdd(&g_sumsq[f], s2);
}

__global__ void bnparam_kernel(const float* __restrict__ g, const float* __restrict__ be) {
    int f = threadIdx.x;
    if (f < DD) {
        float mu = g_sum[f] * (1.0f / NN);
        float var = g_sumsq[f] * (1.0f / NN) - mu * mu;
        float sc = g[f] * rsqrtf(var + BN_EPS);
        g_scale[f] = sc;
        g_shift[f] = be[f] - mu * sc;
    }
}

__global__ void apply_kernel(const float* __restrict__ a, float* __restrict__ o) {
    int i = blockIdx.x * blockDim.x + threadIdx.x;  // float4 index
    if (i < NN * (DD / 4)) {
        int fq = (i & 31) * 4;
        float4 v = ((const float4*)a)[i];
        v.x = fmaxf(fmaf(v.x, g_scale[fq + 0], g_shift[fq + 0]), 0.0f);
        v.y = fmaxf(fmaf(v.y, g_scale[fq + 1], g_shift[fq + 1]), 0.0f);
        v.z = fmaxf(fmaf(v.z, g_scale[fq + 2], g_shift[fq + 2]), 0.0f);
        v.w = fmaxf(fmaf(v.w, g_scale[fq + 3], g_shift[fq + 3]), 0.0f);
        ((float4*)o)[i] = v;
    }
}

// ---------------- final: out = (agg + b3) / max(||row||, 1e-12) ----------
__global__ __launch_bounds__(256) void l2norm_kernel(
    const float* __restrict__ a, const float* __restrict__ b3,
    float* __restrict__ out)
{
    int gw = (blockIdx.x * blockDim.x + threadIdx.x) >> 5;
    int lane = threadIdx.x & 31;
    if (gw >= NN) return;

    float4 v = *(const float4*)(a + (size_t)gw * DD + lane * 4);
    float4 bb = ((const float4*)b3)[lane];
    v.x += bb.x; v.y += bb.y; v.z += bb.z; v.w += bb.w;
    float ss = v.x * v.x + v.y * v.y + v.z * v.z + v.w * v.w;
    #pragma unroll
    for (int off = 16; off; off >>= 1)
        ss += __shfl_xor_sync(0xffffffffu, ss, off);
    float inv = 1.0f / fmaxf(sqrtf(ss), 1e-12f);
    float4 o = make_float4(v.x * inv, v.y * inv, v.z * inv, v.w * inv);
    *(float4*)(out + (size_t)gw * DD + lane * 4) = o;
}

// ---------------- launch ----------------
extern "C" void kernel_launch(void* const* d_in, const int* in_sizes, int n_in,
                              void* d_out, int out_size)
{
    const float* x   = (const float*)d_in[0];
    const int*   ei  = (const int*)d_in[1];
    const float* W1  = (const float*)d_in[2];
    // b1 = d_in[3]  -- mathematically a no-op before BatchNorm
    const float* W2  = (const float*)d_in[4];
    // b2 = d_in[5]  -- no-op before BatchNorm
    const float* W3  = (const float*)d_in[6];
    const float* b3  = (const float*)d_in[7];
    const float* g1  = (const float*)d_in[8];
    const float* be1 = (const float*)d_in[9];
    const float* g2  = (const float*)d_in[10];
    const float* be2 = (const float*)d_in[11];
    float* out = (float*)d_out;

    float* d_h;   cudaGetSymbolAddress((void**)&d_h,   g_h);
    float* d_agg; cudaGetSymbolAddress((void**)&d_agg, g_agg);
    float* d_x2;  cudaGetSymbolAddress((void**)&d_x2,  g_x2);

    const int GEMM_GRID = (NN + 63) / 64;       // 782
    const int WARP_GRID = NN / 8;               // 6250 (8 warps/block, exact)
    const int APPLY_GRID = (NN * (DD / 4) + 255) / 256;

    // --- graph preprocessing ---
    detect_dtype_kernel<<<1, 32>>>(ei);
    zero_deg_kernel<<<(NN + 255) / 256, 256>>>();
    deg_count_kernel<<<(EE + 255) / 256, 256>>>(ei);
    scan_kernel<<<1, 1024>>>();
    dinv_kernel<<<(NN + 255) / 256, 256>>>();
    fill_kernel<<<(EE + 255) / 256, 256>>>(ei);

    // --- layer 1 ---
    gemm_kernel<<<GEMM_GRID, 256>>>(x, W1, d_h, NN);
    agg_kernel<<<WARP_GRID, 256>>>(d_h, d_agg);
    zero_stats_kernel<<<1, 128>>>();
    stats_kernel<<<256, 128>>>(d_agg);
    bnparam_kernel<<<1, 128>>>(g1, be1);
    apply_kernel<<<APPLY_GRID, 256>>>(d_agg, d_x2);

    // --- layer 2 ---
    gemm_kernel<<<GEMM_GRID, 256>>>(d_x2, W2, d_h, NN);
    agg_kernel<<<WARP_GRID, 256>>>(d_h, d_agg);
    zero_stats_kernel<<<1, 128>>>();
    stats_kernel<<<256, 128>>>(d_agg);
    bnparam_kernel<<<1, 128>>>(g2, be2);
    apply_kernel<<<APPLY_GRID, 256>>>(d_agg, d_x2);

    // --- layer 3 ---
    gemm_kernel<<<GEMM_GRID, 256>>>(d_x2, W3, d_h, NN);
    agg_kernel<<<WARP_GRID, 256>>>(d_h, d_agg);
    l2norm_kernel<<<WARP_GRID, 256>>>(d_agg, b3, out);
}

// round 5
// speedup vs baseline: 1.2536x; 1.2536x over previous
#include <cuda_runtime.h>
#include <cuda_bf16.h>
#include <math.h>

#define NN 50000
#define EE 800000
#define DD 128
#define BN_EPS 1e-5f
#define NB 196          // ceil(NN/256) scan blocks

// ---------------- device scratch (no allocations allowed) ----------------
__device__ float g_h[(size_t)NN * DD];    // post-GEMM activations
__device__ float g_agg[(size_t)NN * DD];  // aggregated
__device__ int   g_deg[NN];
__device__ float g_dinv[NN];
__device__ int   g_rowptr[NN + 1];
__device__ int   g_rowcur[NN];
__device__ int   g_col[EE];
__device__ int   g_bsum[256];
__device__ int   g_boff[256];
__device__ float g_sum[DD];
__device__ float g_sumsq[DD];
__device__ float g_scale[DD];
__device__ float g_shift[DD];
__device__ int   g_is64;

// ---------------- edge index access (int32 vs int64 tolerant) -----------
__global__ void detect_dtype_kernel(const int* __restrict__ ei) {
    if (threadIdx.x == 0 && blockIdx.x == 0) {
        int is64 = 1;
        #pragma unroll
        for (int i = 1; i < 16; i += 2)
            if (ei[i] != 0) is64 = 0;
        g_is64 = is64;
    }
}

__device__ __forceinline__ int edge_src(const int* ei, int e) {
    return g_is64 ? ei[2 * e] : ei[e];
}
__device__ __forceinline__ int edge_dst(const int* ei, int e) {
    return g_is64 ? ei[2 * (EE + e)] : ei[EE + e];
}

// ---------------- graph preprocessing ----------------
__global__ void zero_deg_kernel() {
    int i = blockIdx.x * blockDim.x + threadIdx.x;
    if (i < NN) g_deg[i] = 0;
}

__global__ void deg_count_kernel(const int* __restrict__ ei) {
    int e = blockIdx.x * blockDim.x + threadIdx.x;
    if (e < EE) atomicAdd(&g_deg[edge_dst(ei, e)], 1);
}

// ---- multi-block exclusive scan of g_deg -> g_rowptr / g_rowcur / g_dinv ----
__global__ __launch_bounds__(256) void blocksum_kernel() {
    int tid = threadIdx.x;
    int i = blockIdx.x * 256 + tid;
    int v = (i < NN) ? g_deg[i] : 0;
    #pragma unroll
    for (int off = 16; off; off >>= 1)
        v += __shfl_xor_sync(0xffffffffu, v, off);
    __shared__ int ws[8];
    if ((tid & 31) == 0) ws[tid >> 5] = v;
    __syncthreads();
    if (tid == 0) {
        int s = 0;
        #pragma unroll
        for (int w = 0; w < 8; w++) s += ws[w];
        g_bsum[blockIdx.x] = s;
    }
}

__global__ __launch_bounds__(256) void scan_bsums_kernel() {
    __shared__ int sm[256];
    int tid = threadIdx.x;
    int v = (tid < NB) ? g_bsum[tid] : 0;
    sm[tid] = v;
    __syncthreads();
    for (int off = 1; off < 256; off <<= 1) {
        int t = (tid >= off) ? sm[tid - off] : 0;
        __syncthreads();
        sm[tid] += t;
        __syncthreads();
    }
    if (tid < NB) g_boff[tid] = sm[tid] - v;       // exclusive
    if (tid == NB - 1) g_rowptr[NN] = sm[tid];     // total
}

__global__ __launch_bounds__(256) void scatter_scan_kernel() {
    __shared__ int sm[256];
    int tid = threadIdx.x;
    int i = blockIdx.x * 256 + tid;
    int d = (i < NN) ? g_deg[i] : 0;
    sm[tid] = d;
    __syncthreads();
    for (int off = 1; off < 256; off <<= 1) {
        int t = (tid >= off) ? sm[tid - off] : 0;
        __syncthreads();
        sm[tid] += t;
        __syncthreads();
    }
    if (i < NN) {
        int pos = g_boff[blockIdx.x] + sm[tid] - d;  // exclusive prefix
        g_rowptr[i] = pos;
        g_rowcur[i] = pos;
        g_dinv[i] = rsqrtf((float)d + 1.0f);         // +1 self loop
    }
}

__global__ void fill_kernel(const int* __restrict__ ei) {
    int e = blockIdx.x * blockDim.x + threadIdx.x;
    if (e < EE) {
        int d = edge_dst(ei, e);
        int s = edge_src(ei, e);
        int pos = atomicAdd(&g_rowcur[d], 1);
        g_col[pos] = s;
    }
}

// ---------------- SGEMM: C[M,128] = act(A)[M,128] @ W[128,128] -----------
// 64x128 block tile, BK=32, 256 threads, 4x8 register tile per thread.
// BN=true fuses y = relu(a*scale[k] + shift[k]) into the A-tile load.
template<bool BN>
__global__ __launch_bounds__(256) void gemm_kernel(
    const float* __restrict__ A, const float* __restrict__ W,
    float* __restrict__ C, int M)
{
    __shared__ float As[32][68];   // [k][m]
    __shared__ float Ws[32][128];  // [k][n]

    int tid = threadIdx.x;
    int tx = tid & 15;    // col group (8 cols)
    int ty = tid >> 4;    // row group (4 rows)
    int m0 = blockIdx.x * 64;

    float acc[4][8];
    #pragma unroll
    for (int r = 0; r < 4; r++)
        #pragma unroll
        for (int c = 0; c < 8; c++) acc[r][c] = 0.0f;

    for (int k0 = 0; k0 < DD; k0 += 32) {
        // load A chunk (64x32) transposed into smem, optional fused BN+ReLU
        for (int j = tid; j < 512; j += 256) {
            int row = j >> 3;
            int kq = (j & 7) * 4;
            float4 v = make_float4(0.f, 0.f, 0.f, 0.f);
            if (m0 + row < M)
                v = *(const float4*)(A + (size_t)(m0 + row) * DD + k0 + kq);
            if (BN) {
                int f = k0 + kq;
                v.x = fmaxf(fmaf(v.x, g_scale[f + 0], g_shift[f + 0]), 0.0f);
                v.y = fmaxf(fmaf(v.y, g_scale[f + 1], g_shift[f + 1]), 0.0f);
                v.z = fmaxf(fmaf(v.z, g_scale[f + 2], g_shift[f + 2]), 0.0f);
                v.w = fmaxf(fmaf(v.w, g_scale[f + 3], g_shift[f + 3]), 0.0f);
            }
            As[kq + 0][row] = v.x;
            As[kq + 1][row] = v.y;
            As[kq + 2][row] = v.z;
            As[kq + 3][row] = v.w;
        }
        // load W chunk (32x128)
        for (int j = tid; j < 1024; j += 256) {
            int kk = j >> 5;
            int nq = (j & 31) * 4;
            *(float4*)(&Ws[kk][nq]) =
                *(const float4*)(W + (size_t)(k0 + kk) * DD + nq);
        }
        __syncthreads();

        #pragma unroll
        for (int k = 0; k < 32; k++) {
            float4 a  = *(const float4*)(&As[k][ty * 4]);
            float4 w0 = *(const float4*)(&Ws[k][tx * 8]);
            float4 w1 = *(const float4*)(&Ws[k][tx * 8 + 4]);
            float av[4] = {a.x, a.y, a.z, a.w};
            float wv[8] = {w0.x, w0.y, w0.z, w0.w, w1.x, w1.y, w1.z, w1.w};
            #pragma unroll
            for (int r = 0; r < 4; r++)
                #pragma unroll
                for (int c = 0; c < 8; c++)
                    acc[r][c] = fmaf(av[r], wv[c], acc[r][c]);
        }
        __syncthreads();
    }

    #pragma unroll
    for (int r = 0; r < 4; r++) {
        int row = m0 + ty * 4 + r;
        if (row < M) {
            float4 o0 = make_float4(acc[r][0], acc[r][1], acc[r][2], acc[r][3]);
            float4 o1 = make_float4(acc[r][4], acc[r][5], acc[r][6], acc[r][7]);
            *(float4*)(C + (size_t)row * DD + tx * 8)     = o0;
            *(float4*)(C + (size_t)row * DD + tx * 8 + 4) = o1;
        }
    }
}

// ---------------- aggregation + fused BN statistics ----------------------
// one warp per node, lane owns 4 features. CSR gather, no float atomics on
// the aggregate. Per-block smem reduction of per-feature sum/sumsq, one
// global atomic set per block.
__global__ __launch_bounds__(256) void agg_stats_kernel(
    const float* __restrict__ h, float* __restrict__ out)
{
    __shared__ float ssum[DD];
    __shared__ float ssq[DD];
    int tid = threadIdx.x;
    if (tid < DD) { ssum[tid] = 0.0f; ssq[tid] = 0.0f; }
    __syncthreads();

    int gw = (blockIdx.x * blockDim.x + tid) >> 5;
    int lane = tid & 31;

    if (gw < NN) {
        float di = g_dinv[gw];
        float4 acc = *(const float4*)(h + (size_t)gw * DD + lane * 4);
        float wself = di * di;
        acc.x *= wself; acc.y *= wself; acc.z *= wself; acc.w *= wself;

        int beg = g_rowptr[gw];
        int end = g_rowptr[gw + 1];
        for (int e = beg; e < end; e++) {
            int s = g_col[e];
            float w = g_dinv[s] * di;
            float4 v = *(const float4*)(h + (size_t)s * DD + lane * 4);
            acc.x = fmaf(v.x, w, acc.x);
            acc.y = fmaf(v.y, w, acc.y);
            acc.z = fmaf(v.z, w, acc.z);
            acc.w = fmaf(v.w, w, acc.w);
        }
        *(float4*)(out + (size_t)gw * DD + lane * 4) = acc;

        int f = lane * 4;
        atomicAdd(&ssum[f + 0], acc.x);
        atomicAdd(&ssum[f + 1], acc.y);
        atomicAdd(&ssum[f + 2], acc.z);
        atomicAdd(&ssum[f + 3], acc.w);
        atomicAdd(&ssq[f + 0], acc.x * acc.x);
        atomicAdd(&ssq[f + 1], acc.y * acc.y);
        atomicAdd(&ssq[f + 2], acc.z * acc.z);
        atomicAdd(&ssq[f + 3], acc.w * acc.w);
    }
    __syncthreads();
    if (tid < DD) {
        atomicAdd(&g_sum[tid], ssum[tid]);
        atomicAdd(&g_sumsq[tid], ssq[tid]);
    }
}

// ---------------- final aggregation + bias + L2 normalize ----------------
__global__ __launch_bounds__(256) void agg_final_kernel(
    const float* __restrict__ h, const float* __restrict__ b3,
    float* __restrict__ out)
{
    int gw = (blockIdx.x * blockDim.x + threadIdx.x) >> 5;
    int lane = threadIdx.x & 31;
    if (gw >= NN) return;

    float di = g_dinv[gw];
    float4 acc = *(const float4*)(h + (size_t)gw * DD + lane * 4);
    float wself = di * di;
    acc.x *= wself; acc.y *= wself; acc.z *= wself; acc.w *= wself;

    int beg = g_rowptr[gw];
    int end = g_rowptr[gw + 1];
    for (int e = beg; e < end; e++) {
        int s = g_col[e];
        float w = g_dinv[s] * di;
        float4 v = *(const float4*)(h + (size_t)s * DD + lane * 4);
        acc.x = fmaf(v.x, w, acc.x);
        acc.y = fmaf(v.y, w, acc.y);
        acc.z = fmaf(v.z, w, acc.z);
        acc.w = fmaf(v.w, w, acc.w);
    }

    float4 bb = ((const float4*)b3)[lane];
    acc.x += bb.x; acc.y += bb.y; acc.z += bb.z; acc.w += bb.w;
    float ss = acc.x * acc.x + acc.y * acc.y + acc.z * acc.z + acc.w * acc.w;
    #pragma unroll
    for (int off = 16; off; off >>= 1)
        ss += __shfl_xor_sync(0xffffffffu, ss, off);
    float inv = 1.0f / fmaxf(sqrtf(ss), 1e-12f);
    float4 o = make_float4(acc.x * inv, acc.y * inv, acc.z * inv, acc.w * inv);
    *(float4*)(out + (size_t)gw * DD + lane * 4) = o;
}

// ---------------- BatchNorm param finalize ----------------
__global__ void zero_stats_kernel() {
    int f = threadIdx.x;
    if (f < DD) { g_sum[f] = 0.0f; g_sumsq[f] = 0.0f; }
}

__global__ void bnparam_kernel(const float* __restrict__ g, const float* __restrict__ be) {
    int f = threadIdx.x;
    if (f < DD) {
        float mu = g_sum[f] * (1.0f / NN);
        float var = g_sumsq[f] * (1.0f / NN) - mu * mu;
        float sc = g[f] * rsqrtf(var + BN_EPS);
        g_scale[f] = sc;
        g_shift[f] = be[f] - mu * sc;
    }
}

// ---------------- launch ----------------
extern "C" void kernel_launch(void* const* d_in, const int* in_sizes, int n_in,
                              void* d_out, int out_size)
{
    const float* x   = (const float*)d_in[0];
    const int*   ei  = (const int*)d_in[1];
    const float* W1  = (const float*)d_in[2];
    // b1 = d_in[3]  -- mathematically a no-op before BatchNorm
    const float* W2  = (const float*)d_in[4];
    // b2 = d_in[5]  -- no-op before BatchNorm
    const float* W3  = (const float*)d_in[6];
    const float* b3  = (const float*)d_in[7];
    const float* g1  = (const float*)d_in[8];
    const float* be1 = (const float*)d_in[9];
    const float* g2  = (const float*)d_in[10];
    const float* be2 = (const float*)d_in[11];
    float* out = (float*)d_out;

    float* d_h;   cudaGetSymbolAddress((void**)&d_h,   g_h);
    float* d_agg; cudaGetSymbolAddress((void**)&d_agg, g_agg);

    const int GEMM_GRID = (NN + 63) / 64;   // 782
    const int WARP_GRID = NN / 8;           // 6250 (8 warps/block, exact)

    // --- graph preprocessing ---
    detect_dtype_kernel<<<1, 32>>>(ei);
    zero_deg_kernel<<<(NN + 255) / 256, 256>>>();
    deg_count_kernel<<<(EE + 255) / 256, 256>>>(ei);
    blocksum_kernel<<<NB, 256>>>();
    scan_bsums_kernel<<<1, 256>>>();
    scatter_scan_kernel<<<NB, 256>>>();
    fill_kernel<<<(EE + 255) / 256, 256>>>(ei);

    // --- layer 1 ---
    gemm_kernel<false><<<GEMM_GRID, 256>>>(x, W1, d_h, NN);
    zero_stats_kernel<<<1, 128>>>();
    agg_stats_kernel<<<WARP_GRID, 256>>>(d_h, d_agg);
    bnparam_kernel<<<1, 128>>>(g1, be1);

    // --- layer 2 (BN+ReLU fused into A-load) ---
    gemm_kernel<true><<<GEMM_GRID, 256>>>(d_agg, W2, d_h, NN);
    zero_stats_kernel<<<1, 128>>>();
    agg_stats_kernel<<<WARP_GRID, 256>>>(d_h, d_agg);
    bnparam_kernel<<<1, 128>>>(g2, be2);

    // --- layer 3 (BN+ReLU fused into A-load; bias+L2norm fused into agg) ---
    gemm_kernel<true><<<GEMM_GRID, 256>>>(d_agg, W3, d_h, NN);
    agg_final_kernel<<<WARP_GRID, 256>>>(d_h, b3, out);
}

// round 9
// speedup vs baseline: 1.5056x; 1.2010x over previous
#include <cuda_runtime.h>
#include <cuda_bf16.h>
#include <math.h>
#include <stdint.h>

#define NN 50000
#define EE 800000
#define DD 128
#define BN_EPS 1e-5f
#define NB 196          // ceil(NN/256) scan blocks

// ---------------- device scratch (no allocations allowed) ----------------
__device__ float g_h[(size_t)NN * DD];    // post-GEMM activations (fp32)
__device__ float g_agg[(size_t)NN * DD];  // aggregated
__device__ __nv_bfloat16 g_ah[(size_t)NN * DD];  // A hi (bf16)
__device__ __nv_bfloat16 g_al[(size_t)NN * DD];  // A lo (bf16)
__device__ __nv_bfloat16 g_wh[DD * DD];   // W^T hi [n][k]
__device__ __nv_bfloat16 g_wl[DD * DD];   // W^T lo [n][k]
__device__ int   g_deg[NN];
__device__ float g_dinv[NN];
__device__ int   g_rowptr[NN + 1];
__device__ int   g_rowcur[NN];
__device__ int   g_col[EE];
__device__ float g_w[EE];                 // per-edge norm weight
__device__ int   g_bsum[256];
__device__ int   g_boff[256];
__device__ float g_sum[DD];
__device__ float g_sumsq[DD];
__device__ float g_scale[DD];
__device__ float g_shift[DD];
__device__ int   g_is64;

// ---------------- edge index access (int32 vs int64 tolerant) -----------
__global__ void detect_dtype_kernel(const int* __restrict__ ei) {
    if (threadIdx.x == 0 && blockIdx.x == 0) {
        int is64 = 1;
        #pragma unroll
        for (int i = 1; i < 16; i += 2)
            if (ei[i] != 0) is64 = 0;
        g_is64 = is64;
    }
}

__device__ __forceinline__ int edge_src(const int* ei, int e) {
    return g_is64 ? ei[2 * e] : ei[e];
}
__device__ __forceinline__ int edge_dst(const int* ei, int e) {
    return g_is64 ? ei[2 * (EE + e)] : ei[EE + e];
}

// ---------------- graph preprocessing ----------------
__global__ void zero_deg_kernel() {
    int i = blockIdx.x * blockDim.x + threadIdx.x;
    if (i < NN) g_deg[i] = 0;
}

__global__ void deg_count_kernel(const int* __restrict__ ei) {
    int e = blockIdx.x * blockDim.x + threadIdx.x;
    if (e < EE) atomicAdd(&g_deg[edge_dst(ei, e)], 1);
}

__global__ __launch_bounds__(256) void blocksum_kernel() {
    int tid = threadIdx.x;
    int i = blockIdx.x * 256 + tid;
    int v = (i < NN) ? g_deg[i] : 0;
    #pragma unroll
    for (int off = 16; off; off >>= 1)
        v += __shfl_xor_sync(0xffffffffu, v, off);
    __shared__ int ws[8];
    if ((tid & 31) == 0) ws[tid >> 5] = v;
    __syncthreads();
    if (tid == 0) {
        int s = 0;
        #pragma unroll
        for (int w = 0; w < 8; w++) s += ws[w];
        g_bsum[blockIdx.x] = s;
    }
}

__global__ __launch_bounds__(256) void scan_bsums_kernel() {
    __shared__ int sm[256];
    int tid = threadIdx.x;
    int v = (tid < NB) ? g_bsum[tid] : 0;
    sm[tid] = v;
    __syncthreads();
    for (int off = 1; off < 256; off <<= 1) {
        int t = (tid >= off) ? sm[tid - off] : 0;
        __syncthreads();
        sm[tid] += t;
        __syncthreads();
    }
    if (tid < NB) g_boff[tid] = sm[tid] - v;       // exclusive
    if (tid == NB - 1) g_rowptr[NN] = sm[tid];     // total
}

__global__ __launch_bounds__(256) void scatter_scan_kernel() {
    __shared__ int sm[256];
    int tid = threadIdx.x;
    int i = blockIdx.x * 256 + tid;
    int d = (i < NN) ? g_deg[i] : 0;
    sm[tid] = d;
    __syncthreads();
    for (int off = 1; off < 256; off <<= 1) {
        int t = (tid >= off) ? sm[tid - off] : 0;
        __syncthreads();
        sm[tid] += t;
        __syncthreads();
    }
    if (i < NN) {
        int pos = g_boff[blockIdx.x] + sm[tid] - d;
        g_rowptr[i] = pos;
        g_rowcur[i] = pos;
        g_dinv[i] = rsqrtf((float)d + 1.0f);       // +1 self loop
    }
}

__global__ void fill_kernel(const int* __restrict__ ei) {
    int e = blockIdx.x * blockDim.x + threadIdx.x;
    if (e < EE) {
        int d = edge_dst(ei, e);
        int s = edge_src(ei, e);
        int pos = atomicAdd(&g_rowcur[d], 1);
        g_col[pos] = s;
        g_w[pos] = g_dinv[s] * g_dinv[d];
    }
}

// ---------------- fp32 -> bf16 hi/lo split (optional fused BN+ReLU) -----
template<bool BN>
__global__ __launch_bounds__(256) void conv_a_kernel(
    const float* __restrict__ src,
    __nv_bfloat16* __restrict__ hi, __nv_bfloat16* __restrict__ lo)
{
    int i = blockIdx.x * blockDim.x + threadIdx.x;  // float4 index
    if (i >= NN * (DD / 4)) return;
    float4 v = ((const float4*)src)[i];
    if (BN) {
        int f = (i & 31) * 4;
        v.x = fmaxf(fmaf(v.x, g_scale[f + 0], g_shift[f + 0]), 0.0f);
        v.y = fmaxf(fmaf(v.y, g_scale[f + 1], g_shift[f + 1]), 0.0f);
        v.z = fmaxf(fmaf(v.z, g_scale[f + 2], g_shift[f + 2]), 0.0f);
        v.w = fmaxf(fmaf(v.w, g_scale[f + 3], g_shift[f + 3]), 0.0f);
    }
    float a[4] = {v.x, v.y, v.z, v.w};
    uint32_t ph[2], pl[2];
    #pragma unroll
    for (int p = 0; p < 2; p++) {
        __nv_bfloat16 h0 = __float2bfloat16(a[2 * p]);
        __nv_bfloat16 h1 = __float2bfloat16(a[2 * p + 1]);
        __nv_bfloat16 l0 = __float2bfloat16(a[2 * p] - __bfloat162float(h0));
        __nv_bfloat16 l1 = __float2bfloat16(a[2 * p + 1] - __bfloat162float(h1));
        ph[p] = (uint32_t)__bfloat16_as_ushort(h0) | ((uint32_t)__bfloat16_as_ushort(h1) << 16);
        pl[p] = (uint32_t)__bfloat16_as_ushort(l0) | ((uint32_t)__bfloat16_as_ushort(l1) << 16);
    }
    ((uint2*)hi)[i] = make_uint2(ph[0], ph[1]);
    ((uint2*)lo)[i] = make_uint2(pl[0], pl[1]);
}

// W[k][n] -> W^T hi/lo [n][k]
__global__ void conv_w_kernel(const float* __restrict__ W,
                              __nv_bfloat16* __restrict__ wh,
                              __nv_bfloat16* __restrict__ wl)
{
    int i = blockIdx.x * 256 + threadIdx.x;
    if (i >= DD * DD) return;
    int n = i >> 7, k = i & 127;
    float v = W[k * DD + n];
    __nv_bfloat16 h = __float2bfloat16(v);
    __nv_bfloat16 l = __float2bfloat16(v - __bfloat162float(h));
    wh[i] = h;
    wl[i] = l;
}

// ---------------- HMMA GEMM: h[M,128] = A[M,128] @ W[128,128] ----------
// Baseline-PTX tensor cores (mma.sync m16n8k16 bf16 + ldmatrix) — the
// arch-accelerated tcgen05 path is unavailable (ptxas targets sm_103).
// Split precision: Ah@Wh + Ah@Wl + Al@Wh, fp32 accumulate.
// CTA tile 128x128, 8 warps = 4(M) x 2(N), each warp 32x64.
// smem: 4 tiles of 128 rows x 128 bf16, padded pitch 136 (conflict-free).

#define PITCH 136
#define TILE_BYTES (128 * PITCH * 2)   // 34816
#define SM_AHI 0
#define SM_ALO TILE_BYTES
#define SM_WHI (2 * TILE_BYTES)
#define SM_WLO (3 * TILE_BYTES)
#define SM_TOTAL (4 * TILE_BYTES)      // 139264

static __device__ __forceinline__ uint32_t smem_u32(const void* p) {
    uint32_t a;
    asm("{ .reg .u64 t; cvta.to.shared.u64 t, %1; cvt.u32.u64 %0, t; }"
        : "=r"(a) : "l"(p));
    return a;
}

__device__ __forceinline__ void ldm_x4(uint32_t* r, uint32_t addr) {
    asm volatile("ldmatrix.sync.aligned.m8n8.x4.shared.b16 {%0,%1,%2,%3}, [%4];"
                 : "=r"(r[0]), "=r"(r[1]), "=r"(r[2]), "=r"(r[3]) : "r"(addr));
}

__device__ __forceinline__ void mma16816(float* d, const uint32_t* a,
                                         uint32_t b0, uint32_t b1) {
    asm volatile(
        "mma.sync.aligned.m16n8k16.row.col.f32.bf16.bf16.f32 "
        "{%0,%1,%2,%3}, {%4,%5,%6,%7}, {%8,%9}, {%0,%1,%2,%3};"
        : "+f"(d[0]), "+f"(d[1]), "+f"(d[2]), "+f"(d[3])
        : "r"(a[0]), "r"(a[1]), "r"(a[2]), "r"(a[3]), "r"(b0), "r"(b1));
}

__device__ __forceinline__ void load_tile(
    char* smem, int off, const __nv_bfloat16* __restrict__ src,
    int row0, int maxrow, int tid)
{
    // 128 rows x 128 bf16 = 2048 x 16B chunks; 256 threads -> 8 iters
    for (int idx = tid; idx < 2048; idx += 256) {
        int r = idx >> 4;
        int kq = (idx & 15) * 8;
        uint4 v = make_uint4(0u, 0u, 0u, 0u);
        if (row0 + r < maxrow)
            v = *(const uint4*)(src + (size_t)(row0 + r) * DD + kq);
        *(uint4*)(smem + off + ((size_t)r * PITCH + kq) * 2) = v;
    }
}

__global__ __launch_bounds__(256, 1)
void gemm_mma_kernel(const __nv_bfloat16* __restrict__ Ahi,
                     const __nv_bfloat16* __restrict__ Alo,
                     float* __restrict__ C)
{
    extern __shared__ char smem[];
    int tid = threadIdx.x;
    int m0blk = blockIdx.x * 128;

    load_tile(smem, SM_AHI, Ahi, m0blk, NN, tid);
    load_tile(smem, SM_ALO, Alo, m0blk, NN, tid);
    load_tile(smem, SM_WHI, g_wh, 0, DD, tid);
    load_tile(smem, SM_WLO, g_wl, 0, DD, tid);
    __syncthreads();

    uint32_t sbase = smem_u32(smem);
    int wid = tid >> 5;
    int lane = tid & 31;
    int wm = (wid & 3) * 32;        // warp M offset in tile
    int wn = (wid >> 2) * 64;       // warp N offset in tile

    float acc[2][8][4];
    #pragma unroll
    for (int mt = 0; mt < 2; mt++)
        #pragma unroll
        for (int nt = 0; nt < 8; nt++)
            #pragma unroll
            for (int q = 0; q < 4; q++) acc[mt][nt][q] = 0.0f;

    // ldmatrix lane address components
    int a_row = (lane & 7) + 8 * ((lane >> 3) & 1);
    int a_kof = 8 * (lane >> 4);
    int b_nof = (lane & 7) + 8 * (lane >> 4);
    int b_kof = 8 * ((lane >> 3) & 1);

    #pragma unroll
    for (int k0 = 0; k0 < 128; k0 += 16) {
        uint32_t aH[2][4], aL[2][4], bH[4][4], bL[4][4];
        #pragma unroll
        for (int mt = 0; mt < 2; mt++) {
            uint32_t ad = sbase + SM_AHI
                + ((uint32_t)(wm + mt * 16 + a_row) * PITCH + k0 + a_kof) * 2;
            ldm_x4(aH[mt], ad);
            ldm_x4(aL[mt], ad + (SM_ALO - SM_AHI));
        }
        #pragma unroll
        for (int ng = 0; ng < 4; ng++) {
            uint32_t bd = sbase + SM_WHI
                + ((uint32_t)(wn + ng * 16 + b_nof) * PITCH + k0 + b_kof) * 2;
            ldm_x4(bH[ng], bd);
            ldm_x4(bL[ng], bd + (SM_WLO - SM_WHI));
        }
        #pragma unroll
        for (int mt = 0; mt < 2; mt++)
            #pragma unroll
            for (int nt = 0; nt < 8; nt++) {
                int ng = nt >> 1;
                int s = (nt & 1) * 2;
                mma16816(acc[mt][nt], aH[mt], bH[ng][s], bH[ng][s + 1]);
                mma16816(acc[mt][nt], aH[mt], bL[ng][s], bL[ng][s + 1]);
                mma16816(acc[mt][nt], aL[mt], bH[ng][s], bH[ng][s + 1]);
            }
    }

    // store accumulators
    #pragma unroll
    for (int mt = 0; mt < 2; mt++) {
        int row0 = m0blk + wm + mt * 16 + (lane >> 2);
        int row1 = row0 + 8;
        #pragma unroll
        for (int nt = 0; nt < 8; nt++) {
            int col = wn + nt * 8 + (lane & 3) * 2;
            if (row0 < NN)
                *(float2*)(C + (size_t)row0 * DD + col) =
                    make_float2(acc[mt][nt][0], acc[mt][nt][1]);
            if (row1 < NN)
                *(float2*)(C + (size_t)row1 * DD + col) =
                    make_float2(acc[mt][nt][2], acc[mt][nt][3]);
        }
    }
}

// ---------------- aggregation + fused BN statistics ----------------------
__global__ __launch_bounds__(256) void agg_stats_kernel(
    const float* __restrict__ h, float* __restrict__ out)
{
    __shared__ float ssum[DD];
    __shared__ float ssq[DD];
    int tid = threadIdx.x;
    if (tid < DD) { ssum[tid] = 0.0f; ssq[tid] = 0.0f; }
    __syncthreads();

    int gw = (blockIdx.x * blockDim.x + tid) >> 5;
    int lane = tid & 31;

    if (gw < NN) {
        float di = g_dinv[gw];
        float4 acc = *(const float4*)(h + (size_t)gw * DD + lane * 4);
        float wself = di * di;
        acc.x *= wself; acc.y *= wself; acc.z *= wself; acc.w *= wself;

        int beg = g_rowptr[gw];
        int end = g_rowptr[gw + 1];
        int e = beg;
        for (; e + 3 < end; e += 4) {
            int s0 = g_col[e], s1 = g_col[e + 1], s2 = g_col[e + 2], s3 = g_col[e + 3];
            float w0 = g_w[e], w1 = g_w[e + 1], w2 = g_w[e + 2], w3 = g_w[e + 3];
            float4 v0 = *(const float4*)(h + (size_t)s0 * DD + lane * 4);
            float4 v1 = *(const float4*)(h + (size_t)s1 * DD + lane * 4);
            float4 v2 = *(const float4*)(h + (size_t)s2 * DD + lane * 4);
            float4 v3 = *(const float4*)(h + (size_t)s3 * DD + lane * 4);
            acc.x = fmaf(v0.x, w0, acc.x); acc.y = fmaf(v0.y, w0, acc.y);
            acc.z = fmaf(v0.z, w0, acc.z); acc.w = fmaf(v0.w, w0, acc.w);
            acc.x = fmaf(v1.x, w1, acc.x); acc.y = fmaf(v1.y, w1, acc.y);
            acc.z = fmaf(v1.z, w1, acc.z); acc.w = fmaf(v1.w, w1, acc.w);
            acc.x = fmaf(v2.x, w2, acc.x); acc.y = fmaf(v2.y, w2, acc.y);
            acc.z = fmaf(v2.z, w2, acc.z); acc.w = fmaf(v2.w, w2, acc.w);
            acc.x = fmaf(v3.x, w3, acc.x); acc.y = fmaf(v3.y, w3, acc.y);
            acc.z = fmaf(v3.z, w3, acc.z); acc.w = fmaf(v3.w, w3, acc.w);
        }
        for (; e < end; e++) {
            int s = g_col[e];
            float w = g_w[e];
            float4 v = *(const float4*)(h + (size_t)s * DD + lane * 4);
            acc.x = fmaf(v.x, w, acc.x); acc.y = fmaf(v.y, w, acc.y);
            acc.z = fmaf(v.z, w, acc.z); acc.w = fmaf(v.w, w, acc.w);
        }
        *(float4*)(out + (size_t)gw * DD + lane * 4) = acc;

        int f = lane * 4;
        atomicAdd(&ssum[f + 0], acc.x);
        atomicAdd(&ssum[f + 1], acc.y);
        atomicAdd(&ssum[f + 2], acc.z);
        atomicAdd(&ssum[f + 3], acc.w);
        atomicAdd(&ssq[f + 0], acc.x * acc.x);
        atomicAdd(&ssq[f + 1], acc.y * acc.y);
        atomicAdd(&ssq[f + 2], acc.z * acc.z);
        atomicAdd(&ssq[f + 3], acc.w * acc.w);
    }
    __syncthreads();
    if (tid < DD) {
        atomicAdd(&g_sum[tid], ssum[tid]);
        atomicAdd(&g_sumsq[tid], ssq[tid]);
    }
}

// ---------------- final aggregation + bias + L2 normalize ----------------
__global__ __launch_bounds__(256) void agg_final_kernel(
    const float* __restrict__ h, const float* __restrict__ b3,
    float* __restrict__ out)
{
    int gw = (blockIdx.x * blockDim.x + threadIdx.x) >> 5;
    int lane = threadIdx.x & 31;
    if (gw >= NN) return;

    float di = g_dinv[gw];
    float4 acc = *(const float4*)(h + (size_t)gw * DD + lane * 4);
    float wself = di * di;
    acc.x *= wself; acc.y *= wself; acc.z *= wself; acc.w *= wself;

    int beg = g_rowptr[gw];
    int end = g_rowptr[gw + 1];
    int e = beg;
    for (; e + 3 < end; e += 4) {
        int s0 = g_col[e], s1 = g_col[e + 1], s2 = g_col[e + 2], s3 = g_col[e + 3];
        float w0 = g_w[e], w1 = g_w[e + 1], w2 = g_w[e + 2], w3 = g_w[e + 3];
        float4 v0 = *(const float4*)(h + (size_t)s0 * DD + lane * 4);
        float4 v1 = *(const float4*)(h + (size_t)s1 * DD + lane * 4);
        float4 v2 = *(const float4*)(h + (size_t)s2 * DD + lane * 4);
        float4 v3 = *(const float4*)(h + (size_t)s3 * DD + lane * 4);
        acc.x = fmaf(v0.x, w0, acc.x); acc.y = fmaf(v0.y, w0, acc.y);
        acc.z = fmaf(v0.z, w0, acc.z); acc.w = fmaf(v0.w, w0, acc.w);
        acc.x = fmaf(v1.x, w1, acc.x); acc.y = fmaf(v1.y, w1, acc.y);
        acc.z = fmaf(v1.z, w1, acc.z); acc.w = fmaf(v1.w, w1, acc.w);
        acc.x = fmaf(v2.x, w2, acc.x); acc.y = fmaf(v2.y, w2, acc.y);
        acc.z = fmaf(v2.z, w2, acc.z); acc.w = fmaf(v2.w, w2, acc.w);
        acc.x = fmaf(v3.x, w3, acc.x); acc.y = fmaf(v3.y, w3, acc.y);
        acc.z = fmaf(v3.z, w3, acc.z); acc.w = fmaf(v3.w, w3, acc.w);
    }
    for (; e < end; e++) {
        int s = g_col[e];
        float w = g_w[e];
        float4 v = *(const float4*)(h + (size_t)s * DD + lane * 4);
        acc.x = fmaf(v.x, w, acc.x); acc.y = fmaf(v.y, w, acc.y);
        acc.z = fmaf(v.z, w, acc.z); acc.w = fmaf(v.w, w, acc.w);
    }

    float4 bb = ((const float4*)b3)[lane];
    acc.x += bb.x; acc.y += bb.y; acc.z += bb.z; acc.w += bb.w;
    float ss = acc.x * acc.x + acc.y * acc.y + acc.z * acc.z + acc.w * acc.w;
    #pragma unroll
    for (int off = 16; off; off >>= 1)
        ss += __shfl_xor_sync(0xffffffffu, ss, off);
    float inv = 1.0f / fmaxf(sqrtf(ss), 1e-12f);
    float4 o = make_float4(acc.x * inv, acc.y * inv, acc.z * inv, acc.w * inv);
    *(float4*)(out + (size_t)gw * DD + lane * 4) = o;
}

// ---------------- BatchNorm params ----------------
__global__ void zero_stats_kernel() {
    int f = threadIdx.x;
    if (f < DD) { g_sum[f] = 0.0f; g_sumsq[f] = 0.0f; }
}

__global__ void bnparam_kernel(const float* __restrict__ g, const float* __restrict__ be) {
    int f = threadIdx.x;
    if (f < DD) {
        float mu = g_sum[f] * (1.0f / NN);
        float var = g_sumsq[f] * (1.0f / NN) - mu * mu;
        float sc = g[f] * rsqrtf(var + BN_EPS);
        g_scale[f] = sc;
        g_shift[f] = be[f] - mu * sc;
    }
}

// ---------------- launch ----------------
extern "C" void kernel_launch(void* const* d_in, const int* in_sizes, int n_in,
                              void* d_out, int out_size)
{
    const float* x   = (const float*)d_in[0];
    const int*   ei  = (const int*)d_in[1];
    const float* W1  = (const float*)d_in[2];
    // b1 = d_in[3]  -- no-op before BatchNorm
    const float* W2  = (const float*)d_in[4];
    // b2 = d_in[5]  -- no-op before BatchNorm
    const float* W3  = (const float*)d_in[6];
    const float* b3  = (const float*)d_in[7];
    const float* g1  = (const float*)d_in[8];
    const float* be1 = (const float*)d_in[9];
    const float* g2  = (const float*)d_in[10];
    const float* be2 = (const float*)d_in[11];
    float* out = (float*)d_out;

    float* d_h;   cudaGetSymbolAddress((void**)&d_h,   g_h);
    float* d_agg; cudaGetSymbolAddress((void**)&d_agg, g_agg);
    __nv_bfloat16* d_ah; cudaGetSymbolAddress((void**)&d_ah, g_ah);
    __nv_bfloat16* d_al; cudaGetSymbolAddress((void**)&d_al, g_al);

    static int smem_set = 0;
    if (!smem_set) {
        cudaFuncSetAttribute(gemm_mma_kernel,
                             cudaFuncAttributeMaxDynamicSharedMemorySize, SM_TOTAL);
        smem_set = 1;
    }

    const int GEMM_GRID = (NN + 127) / 128;   // 391
    const int WARP_GRID = NN / 8;             // 6250
    const int CONV_GRID = (NN * (DD / 4) + 255) / 256;

    __nv_bfloat16* d_wh; cudaGetSymbolAddress((void**)&d_wh, g_wh);
    __nv_bfloat16* d_wl; cudaGetSymbolAddress((void**)&d_wl, g_wl);

    // --- graph preprocessing ---
    detect_dtype_kernel<<<1, 32>>>(ei);
    zero_deg_kernel<<<(NN + 255) / 256, 256>>>();
    deg_count_kernel<<<(EE + 255) / 256, 256>>>(ei);
    blocksum_kernel<<<NB, 256>>>();
    scan_bsums_kernel<<<1, 256>>>();
    scatter_scan_kernel<<<NB, 256>>>();
    fill_kernel<<<(EE + 255) / 256, 256>>>(ei);

    // --- layer 1 ---
    conv_w_kernel<<<64, 256>>>(W1, d_wh, d_wl);
    conv_a_kernel<false><<<CONV_GRID, 256>>>(x, d_ah, d_al);
    gemm_mma_kernel<<<GEMM_GRID, 256, SM_TOTAL>>>(d_ah, d_al, d_h);
    zero_stats_kernel<<<1, 128>>>();
    agg_stats_kernel<<<WARP_GRID, 256>>>(d_h, d_agg);
    bnparam_kernel<<<1, 128>>>(g1, be1);

    // --- layer 2 (BN+ReLU fused into conversion) ---
    conv_w_kernel<<<64, 256>>>(W2, d_wh, d_wl);
    conv_a_kernel<true><<<CONV_GRID, 256>>>(d_agg, d_ah, d_al);
    gemm_mma_kernel<<<GEMM_GRID, 256, SM_TOTAL>>>(d_ah, d_al, d_h);
    zero_stats_kernel<<<1, 128>>>();
    agg_stats_kernel<<<WARP_GRID, 256>>>(d_h, d_agg);
    bnparam_kernel<<<1, 128>>>(g2, be2);

    // --- layer 3 (bias + L2norm fused into final aggregation) ---
    conv_w_kernel<<<64, 256>>>(W3, d_wh, d_wl);
    conv_a_kernel<true><<<CONV_GRID, 256>>>(d_agg, d_ah, d_al);
    gemm_mma_kernel<<<GEMM_GRID, 256, SM_TOTAL>>>(d_ah, d_al, d_h);
    agg_final_kernel<<<WARP_GRID, 256>>>(d_h, b3, out);
}

// round 10
// speedup vs baseline: 1.5578x; 1.0347x over previous
#include <cuda_runtime.h>
#include <cuda_bf16.h>
#include <math.h>
#include <stdint.h>

#define NN 50000
#define EE 800000
#define DD 128
#define BN_EPS 1e-5f
#define NB 196          // ceil(NN/256) scan blocks

// ---------------- device scratch (no allocations allowed) ----------------
__device__ float g_h[(size_t)NN * DD];    // post-GEMM activations (fp32)
__device__ float g_agg[(size_t)NN * DD];  // aggregated
__device__ __nv_bfloat16 g_wh[DD * DD];   // W^T hi [n][k]
__device__ __nv_bfloat16 g_wl[DD * DD];   // W^T lo [n][k]
__device__ int   g_deg[NN];
__device__ float g_dinv[NN];
__device__ int   g_rowptr[NN + 1];
__device__ int   g_rowcur[NN];
__device__ int   g_col[EE];
__device__ float g_w[EE];                 // per-edge norm weight
__device__ int   g_bsum[256];
__device__ int   g_boff[256];
__device__ float g_sum[DD];
__device__ float g_sumsq[DD];
__device__ float g_scale[DD];
__device__ float g_shift[DD];
__device__ int   g_is64;

// ---------------- edge index access (int32 vs int64 tolerant) -----------
__device__ __forceinline__ int edge_src(const int* ei, int e) {
    return g_is64 ? ei[2 * e] : ei[e];
}
__device__ __forceinline__ int edge_dst(const int* ei, int e) {
    return g_is64 ? ei[2 * (EE + e)] : ei[EE + e];
}

// ---------------- graph preprocessing ----------------
// zero degrees + detect edge dtype + zero BN stats (one launch)
__global__ void init_kernel(const int* __restrict__ ei) {
    int i = blockIdx.x * blockDim.x + threadIdx.x;
    if (i < NN) g_deg[i] = 0;
    if (i < DD) { g_sum[i] = 0.0f; g_sumsq[i] = 0.0f; }
    if (i == 0) {
        // int64 values < 2^31 -> every odd int32 slot is 0.
        int is64 = 1;
        #pragma unroll
        for (int j = 1; j < 16; j += 2)
            if (ei[j] != 0) is64 = 0;
        g_is64 = is64;
    }
}

__global__ void deg_count_kernel(const int* __restrict__ ei) {
    int e = blockIdx.x * blockDim.x + threadIdx.x;
    if (e < EE) atomicAdd(&g_deg[edge_dst(ei, e)], 1);
}

__global__ __launch_bounds__(256) void blocksum_kernel() {
    int tid = threadIdx.x;
    int i = blockIdx.x * 256 + tid;
    int v = (i < NN) ? g_deg[i] : 0;
    #pragma unroll
    for (int off = 16; off; off >>= 1)
        v += __shfl_xor_sync(0xffffffffu, v, off);
    __shared__ int ws[8];
    if ((tid & 31) == 0) ws[tid >> 5] = v;
    __syncthreads();
    if (tid == 0) {
        int s = 0;
        #pragma unroll
        for (int w = 0; w < 8; w++) s += ws[w];
        g_bsum[blockIdx.x] = s;
    }
}

__global__ __launch_bounds__(256) void scan_bsums_kernel() {
    __shared__ int sm[256];
    int tid = threadIdx.x;
    int v = (tid < NB) ? g_bsum[tid] : 0;
    sm[tid] = v;
    __syncthreads();
    for (int off = 1; off < 256; off <<= 1) {
        int t = (tid >= off) ? sm[tid - off] : 0;
        __syncthreads();
        sm[tid] += t;
        __syncthreads();
    }
    if (tid < NB) g_boff[tid] = sm[tid] - v;       // exclusive
    if (tid == NB - 1) g_rowptr[NN] = sm[tid];     // total
}

__global__ __launch_bounds__(256) void scatter_scan_kernel() {
    __shared__ int sm[256];
    int tid = threadIdx.x;
    int i = blockIdx.x * 256 + tid;
    int d = (i < NN) ? g_deg[i] : 0;
    sm[tid] = d;
    __syncthreads();
    for (int off = 1; off < 256; off <<= 1) {
        int t = (tid >= off) ? sm[tid - off] : 0;
        __syncthreads();
        sm[tid] += t;
        __syncthreads();
    }
    if (i < NN) {
        int pos = g_boff[blockIdx.x] + sm[tid] - d;
        g_rowptr[i] = pos;
        g_rowcur[i] = pos;
        g_dinv[i] = rsqrtf((float)d + 1.0f);       // +1 self loop
    }
}

__global__ void fill_kernel(const int* __restrict__ ei) {
    int e = blockIdx.x * blockDim.x + threadIdx.x;
    if (e < EE) {
        int d = edge_dst(ei, e);
        int s = edge_src(ei, e);
        int pos = atomicAdd(&g_rowcur[d], 1);
        g_col[pos] = s;
        g_w[pos] = g_dinv[s] * g_dinv[d];
    }
}

// W[k][n] -> W^T hi/lo [n][k]
__global__ void conv_w_kernel(const float* __restrict__ W,
                              __nv_bfloat16* __restrict__ wh,
                              __nv_bfloat16* __restrict__ wl)
{
    int i = blockIdx.x * 256 + threadIdx.x;
    if (i >= DD * DD) return;
    int n = i >> 7, k = i & 127;
    float v = W[k * DD + n];
    __nv_bfloat16 h = __float2bfloat16(v);
    __nv_bfloat16 l = __float2bfloat16(v - __bfloat162float(h));
    wh[i] = h;
    wl[i] = l;
}

// ---------------- HMMA GEMM: h[M,128] = act(A)[M,128] @ W[128,128] -----
// mma.sync m16n8k16 bf16 + ldmatrix (tcgen05 not expressible: ptxas targets
// plain sm_103). Split precision Ah@Wh + Ah@Wl + Al@Wh, fp32 accumulate.
// BN+ReLU+hi/lo-split fused into the fp32 A-tile smem load (replaces the
// old conv_a pass; identical math bit-for-bit).
// CTA tile 128x128, 8 warps = 4(M) x 2(N), each warp 32x64.

#define PITCH 136
#define TILE_BYTES (128 * PITCH * 2)   // 34816
#define SM_AHI 0
#define SM_ALO TILE_BYTES
#define SM_WHI (2 * TILE_BYTES)
#define SM_WLO (3 * TILE_BYTES)
#define SM_TOTAL (4 * TILE_BYTES)      // 139264

static __device__ __forceinline__ uint32_t smem_u32(const void* p) {
    uint32_t a;
    asm("{ .reg .u64 t; cvta.to.shared.u64 t, %1; cvt.u32.u64 %0, t; }"
        : "=r"(a) : "l"(p));
    return a;
}

__device__ __forceinline__ void ldm_x4(uint32_t* r, uint32_t addr) {
    asm volatile("ldmatrix.sync.aligned.m8n8.x4.shared.b16 {%0,%1,%2,%3}, [%4];"
                 : "=r"(r[0]), "=r"(r[1]), "=r"(r[2]), "=r"(r[3]) : "r"(addr));
}

__device__ __forceinline__ void mma16816(float* d, const uint32_t* a,
                                         uint32_t b0, uint32_t b1) {
    asm volatile(
        "mma.sync.aligned.m16n8k16.row.col.f32.bf16.bf16.f32 "
        "{%0,%1,%2,%3}, {%4,%5,%6,%7}, {%8,%9}, {%0,%1,%2,%3};"
        : "+f"(d[0]), "+f"(d[1]), "+f"(d[2]), "+f"(d[3])
        : "r"(a[0]), "r"(a[1]), "r"(a[2]), "r"(a[3]), "r"(b0), "r"(b1));
}

// bf16 W tiles: 128 rows x 128 bf16 = 2048 x 16B chunks
__device__ __forceinline__ void load_tile_bf16(
    char* smem, int off, const __nv_bfloat16* __restrict__ src, int tid)
{
    for (int idx = tid; idx < 2048; idx += 256) {
        int r = idx >> 4;
        int kq = (idx & 15) * 8;
        uint4 v = *(const uint4*)(src + (size_t)r * DD + kq);
        *(uint4*)(smem + off + ((size_t)r * PITCH + kq) * 2) = v;
    }
}

// fp32 A tile with fused BN+ReLU and hi/lo split -> two bf16 smem tiles.
template<bool BN>
__device__ __forceinline__ void load_split_tile(
    char* smem, const float* __restrict__ A, int row0, int tid)
{
    // 128 rows x 32 float4 chunks = 4096; 256 threads -> 16 iters
    for (int idx = tid; idx < 4096; idx += 256) {
        int r = idx >> 5;
        int c4 = (idx & 31) * 4;
        float4 v = make_float4(0.f, 0.f, 0.f, 0.f);
        if (row0 + r < NN)
            v = *(const float4*)(A + (size_t)(row0 + r) * DD + c4);
        if (BN) {
            v.x = fmaxf(fmaf(v.x, g_scale[c4 + 0], g_shift[c4 + 0]), 0.0f);
            v.y = fmaxf(fmaf(v.y, g_scale[c4 + 1], g_shift[c4 + 1]), 0.0f);
            v.z = fmaxf(fmaf(v.z, g_scale[c4 + 2], g_shift[c4 + 2]), 0.0f);
            v.w = fmaxf(fmaf(v.w, g_scale[c4 + 3], g_shift[c4 + 3]), 0.0f);
        }
        float a[4] = {v.x, v.y, v.z, v.w};
        uint32_t ph[2], pl[2];
        #pragma unroll
        for (int p = 0; p < 2; p++) {
            __nv_bfloat16 h0 = __float2bfloat16(a[2 * p]);
            __nv_bfloat16 h1 = __float2bfloat16(a[2 * p + 1]);
            __nv_bfloat16 l0 = __float2bfloat16(a[2 * p] - __bfloat162float(h0));
            __nv_bfloat16 l1 = __float2bfloat16(a[2 * p + 1] - __bfloat162float(h1));
            ph[p] = (uint32_t)__bfloat16_as_ushort(h0) | ((uint32_t)__bfloat16_as_ushort(h1) << 16);
            pl[p] = (uint32_t)__bfloat16_as_ushort(l0) | ((uint32_t)__bfloat16_as_ushort(l1) << 16);
        }
        size_t boff = ((size_t)r * PITCH + c4) * 2;
        *(uint2*)(smem + SM_AHI + boff) = make_uint2(ph[0], ph[1]);
        *(uint2*)(smem + SM_ALO + boff) = make_uint2(pl[0], pl[1]);
    }
}

template<bool BN>
__global__ __launch_bounds__(256, 1)
void gemm_mma_kernel(const float* __restrict__ A, float* __restrict__ C)
{
    extern __shared__ char smem[];
    int tid = threadIdx.x;
    int m0blk = blockIdx.x * 128;

    load_split_tile<BN>(smem, A, m0blk, tid);
    load_tile_bf16(smem, SM_WHI, g_wh, tid);
    load_tile_bf16(smem, SM_WLO, g_wl, tid);
    __syncthreads();

    uint32_t sbase = smem_u32(smem);
    int wid = tid >> 5;
    int lane = tid & 31;
    int wm = (wid & 3) * 32;        // warp M offset in tile
    int wn = (wid >> 2) * 64;       // warp N offset in tile

    float acc[2][8][4];
    #pragma unroll
    for (int mt = 0; mt < 2; mt++)
        #pragma unroll
        for (int nt = 0; nt < 8; nt++)
            #pragma unroll
            for (int q = 0; q < 4; q++) acc[mt][nt][q] = 0.0f;

    // ldmatrix lane address components
    int a_row = (lane & 7) + 8 * ((lane >> 3) & 1);
    int a_kof = 8 * (lane >> 4);
    int b_nof = (lane & 7) + 8 * (lane >> 4);
    int b_kof = 8 * ((lane >> 3) & 1);

    #pragma unroll
    for (int k0 = 0; k0 < 128; k0 += 16) {
        uint32_t aH[2][4], aL[2][4], bH[4][4], bL[4][4];
        #pragma unroll
        for (int mt = 0; mt < 2; mt++) {
            uint32_t ad = sbase + SM_AHI
                + ((uint32_t)(wm + mt * 16 + a_row) * PITCH + k0 + a_kof) * 2;
            ldm_x4(aH[mt], ad);
            ldm_x4(aL[mt], ad + (SM_ALO - SM_AHI));
        }
        #pragma unroll
        for (int ng = 0; ng < 4; ng++) {
            uint32_t bd = sbase + SM_WHI
                + ((uint32_t)(wn + ng * 16 + b_nof) * PITCH + k0 + b_kof) * 2;
            ldm_x4(bH[ng], bd);
            ldm_x4(bL[ng], bd + (SM_WLO - SM_WHI));
        }
        #pragma unroll
        for (int mt = 0; mt < 2; mt++)
            #pragma unroll
            for (int nt = 0; nt < 8; nt++) {
                int ng = nt >> 1;
                int s = (nt & 1) * 2;
                mma16816(acc[mt][nt], aH[mt], bH[ng][s], bH[ng][s + 1]);
                mma16816(acc[mt][nt], aH[mt], bL[ng][s], bL[ng][s + 1]);
                mma16816(acc[mt][nt], aL[mt], bH[ng][s], bH[ng][s + 1]);
            }
    }

    // store accumulators
    #pragma unroll
    for (int mt = 0; mt < 2; mt++) {
        int row0 = m0blk + wm + mt * 16 + (lane >> 2);
        int row1 = row0 + 8;
        #pragma unroll
        for (int nt = 0; nt < 8; nt++) {
            int col = wn + nt * 8 + (lane & 3) * 2;
            if (row0 < NN)
                *(float2*)(C + (size_t)row0 * DD + col) =
                    make_float2(acc[mt][nt][0], acc[mt][nt][1]);
            if (row1 < NN)
                *(float2*)(C + (size_t)row1 * DD + col) =
                    make_float2(acc[mt][nt][2], acc[mt][nt][3]);
        }
    }
}

// ---------------- aggregation + fused BN statistics ----------------------
__global__ __launch_bounds__(256) void agg_stats_kernel(
    const float* __restrict__ h, float* __restrict__ out)
{
    __shared__ float ssum[DD];
    __shared__ float ssq[DD];
    int tid = threadIdx.x;
    if (tid < DD) { ssum[tid] = 0.0f; ssq[tid] = 0.0f; }
    __syncthreads();

    int gw = (blockIdx.x * blockDim.x + tid) >> 5;
    int lane = tid & 31;

    if (gw < NN) {
        float di = g_dinv[gw];
        float4 acc = *(const float4*)(h + (size_t)gw * DD + lane * 4);
        float wself = di * di;
        acc.x *= wself; acc.y *= wself; acc.z *= wself; acc.w *= wself;

        int beg = g_rowptr[gw];
        int end = g_rowptr[gw + 1];
        int e = beg;
        for (; e + 3 < end; e += 4) {
            int s0 = g_col[e], s1 = g_col[e + 1], s2 = g_col[e + 2], s3 = g_col[e + 3];
            float w0 = g_w[e], w1 = g_w[e + 1], w2 = g_w[e + 2], w3 = g_w[e + 3];
            float4 v0 = *(const float4*)(h + (size_t)s0 * DD + lane * 4);
            float4 v1 = *(const float4*)(h + (size_t)s1 * DD + lane * 4);
            float4 v2 = *(const float4*)(h + (size_t)s2 * DD + lane * 4);
            float4 v3 = *(const float4*)(h + (size_t)s3 * DD + lane * 4);
            acc.x = fmaf(v0.x, w0, acc.x); acc.y = fmaf(v0.y, w0, acc.y);
            acc.z = fmaf(v0.z, w0, acc.z); acc.w = fmaf(v0.w, w0, acc.w);
            acc.x = fmaf(v1.x, w1, acc.x); acc.y = fmaf(v1.y, w1, acc.y);
            acc.z = fmaf(v1.z, w1, acc.z); acc.w = fmaf(v1.w, w1, acc.w);
            acc.x = fmaf(v2.x, w2, acc.x); acc.y = fmaf(v2.y, w2, acc.y);
            acc.z = fmaf(v2.z, w2, acc.z); acc.w = fmaf(v2.w, w2, acc.w);
            acc.x = fmaf(v3.x, w3, acc.x); acc.y = fmaf(v3.y, w3, acc.y);
            acc.z = fmaf(v3.z, w3, acc.z); acc.w = fmaf(v3.w, w3, acc.w);
        }
        for (; e < end; e++) {
            int s = g_col[e];
            float w = g_w[e];
            float4 v = *(const float4*)(h + (size_t)s * DD + lane * 4);
            acc.x = fmaf(v.x, w, acc.x); acc.y = fmaf(v.y, w, acc.y);
            acc.z = fmaf(v.z, w, acc.z); acc.w = fmaf(v.w, w, acc.w);
        }
        *(float4*)(out + (size_t)gw * DD + lane * 4) = acc;

        int f = lane * 4;
        atomicAdd(&ssum[f + 0], acc.x);
        atomicAdd(&ssum[f + 1], acc.y);
        atomicAdd(&ssum[f + 2], acc.z);
        atomicAdd(&ssum[f + 3], acc.w);
        atomicAdd(&ssq[f + 0], acc.x * acc.x);
        atomicAdd(&ssq[f + 1], acc.y * acc.y);
        atomicAdd(&ssq[f + 2], acc.z * acc.z);
        atomicAdd(&ssq[f + 3], acc.w * acc.w);
    }
    __syncthreads();
    if (tid < DD) {
        atomicAdd(&g_sum[tid], ssum[tid]);
        atomicAdd(&g_sumsq[tid], ssq[tid]);
    }
}

// ---------------- final aggregation + bias + L2 normalize ----------------
__global__ __launch_bounds__(256) void agg_final_kernel(
    const float* __restrict__ h, const float* __restrict__ b3,
    float* __restrict__ out)
{
    int gw = (blockIdx.x * blockDim.x + threadIdx.x) >> 5;
    int lane = threadIdx.x & 31;
    if (gw >= NN) return;

    float di = g_dinv[gw];
    float4 acc = *(const float4*)(h + (size_t)gw * DD + lane * 4);
    float wself = di * di;
    acc.x *= wself; acc.y *= wself; acc.z *= wself; acc.w *= wself;

    int beg = g_rowptr[gw];
    int end = g_rowptr[gw + 1];
    int e = beg;
    for (; e + 3 < end; e += 4) {
        int s0 = g_col[e], s1 = g_col[e + 1], s2 = g_col[e + 2], s3 = g_col[e + 3];
        float w0 = g_w[e], w1 = g_w[e + 1], w2 = g_w[e + 2], w3 = g_w[e + 3];
        float4 v0 = *(const float4*)(h + (size_t)s0 * DD + lane * 4);
        float4 v1 = *(const float4*)(h + (size_t)s1 * DD + lane * 4);
        float4 v2 = *(const float4*)(h + (size_t)s2 * DD + lane * 4);
        float4 v3 = *(const float4*)(h + (size_t)s3 * DD + lane * 4);
        acc.x = fmaf(v0.x, w0, acc.x); acc.y = fmaf(v0.y, w0, acc.y);
        acc.z = fmaf(v0.z, w0, acc.z); acc.w = fmaf(v0.w, w0, acc.w);
        acc.x = fmaf(v1.x, w1, acc.x); acc.y = fmaf(v1.y, w1, acc.y);
        acc.z = fmaf(v1.z, w1, acc.z); acc.w = fmaf(v1.w, w1, acc.w);
        acc.x = fmaf(v2.x, w2, acc.x); acc.y = fmaf(v2.y, w2, acc.y);
        acc.z = fmaf(v2.z, w2, acc.z); acc.w = fmaf(v2.w, w2, acc.w);
        acc.x = fmaf(v3.x, w3, acc.x); acc.y = fmaf(v3.y, w3, acc.y);
        acc.z = fmaf(v3.z, w3, acc.z); acc.w = fmaf(v3.w, w3, acc.w);
    }
    for (; e < end; e++) {
        int s = g_col[e];
        float w = g_w[e];
        float4 v = *(const float4*)(h + (size_t)s * DD + lane * 4);
        acc.x = fmaf(v.x, w, acc.x); acc.y = fmaf(v.y, w, acc.y);
        acc.z = fmaf(v.z, w, acc.z); acc.w = fmaf(v.w, w, acc.w);
    }

    float4 bb = ((const float4*)b3)[lane];
    acc.x += bb.x; acc.y += bb.y; acc.z += bb.z; acc.w += bb.w;
    float ss = acc.x * acc.x + acc.y * acc.y + acc.z * acc.z + acc.w * acc.w;
    #pragma unroll
    for (int off = 16; off; off >>= 1)
        ss += __shfl_xor_sync(0xffffffffu, ss, off);
    float inv = 1.0f / fmaxf(sqrtf(ss), 1e-12f);
    float4 o = make_float4(acc.x * inv, acc.y * inv, acc.z * inv, acc.w * inv);
    *(float4*)(out + (size_t)gw * DD + lane * 4) = o;
}

// ---------------- BatchNorm params (consumes + re-zeroes stats) ----------
__global__ void bnparam_kernel(const float* __restrict__ g, const float* __restrict__ be) {
    int f = threadIdx.x;
    if (f < DD) {
        float mu = g_sum[f] * (1.0f / NN);
        float var = g_sumsq[f] * (1.0f / NN) - mu * mu;
        float sc = g[f] * rsqrtf(var + BN_EPS);
        g_scale[f] = sc;
        g_shift[f] = be[f] - mu * sc;
        g_sum[f] = 0.0f;       // ready for next layer's agg_stats
        g_sumsq[f] = 0.0f;
    }
}

// ---------------- launch ----------------
extern "C" void kernel_launch(void* const* d_in, const int* in_sizes, int n_in,
                              void* d_out, int out_size)
{
    const float* x   = (const float*)d_in[0];
    const int*   ei  = (const int*)d_in[1];
    const float* W1  = (const float*)d_in[2];
    // b1 = d_in[3]  -- no-op before BatchNorm
    const float* W2  = (const float*)d_in[4];
    // b2 = d_in[5]  -- no-op before BatchNorm
    const float* W3  = (const float*)d_in[6];
    const float* b3  = (const float*)d_in[7];
    const float* g1  = (const float*)d_in[8];
    const float* be1 = (const float*)d_in[9];
    const float* g2  = (const float*)d_in[10];
    const float* be2 = (const float*)d_in[11];
    float* out = (float*)d_out;

    float* d_h;   cudaGetSymbolAddress((void**)&d_h,   g_h);
    float* d_agg; cudaGetSymbolAddress((void**)&d_agg, g_agg);
    __nv_bfloat16* d_wh; cudaGetSymbolAddress((void**)&d_wh, g_wh);
    __nv_bfloat16* d_wl; cudaGetSymbolAddress((void**)&d_wl, g_wl);

    static int smem_set = 0;
    if (!smem_set) {
        cudaFuncSetAttribute(gemm_mma_kernel<false>,
                             cudaFuncAttributeMaxDynamicSharedMemorySize, SM_TOTAL);
        cudaFuncSetAttribute(gemm_mma_kernel<true>,
                             cudaFuncAttributeMaxDynamicSharedMemorySize, SM_TOTAL);
        smem_set = 1;
    }

    const int GEMM_GRID = (NN + 127) / 128;   // 391
    const int WARP_GRID = NN / 8;             // 6250

    // --- graph preprocessing ---
    init_kernel<<<(NN + 255) / 256, 256>>>(ei);
    deg_count_kernel<<<(EE + 255) / 256, 256>>>(ei);
    blocksum_kernel<<<NB, 256>>>();
    scan_bsums_kernel<<<1, 256>>>();
    scatter_scan_kernel<<<NB, 256>>>();
    fill_kernel<<<(EE + 255) / 256, 256>>>(ei);

    // --- layer 1 ---
    conv_w_kernel<<<64, 256>>>(W1, d_wh, d_wl);
    gemm_mma_kernel<false><<<GEMM_GRID, 256, SM_TOTAL>>>(x, d_h);
    agg_stats_kernel<<<WARP_GRID, 256>>>(d_h, d_agg);
    bnparam_kernel<<<1, 128>>>(g1, be1);

    // --- layer 2 (BN+ReLU+split fused into GEMM A-load) ---
    conv_w_kernel<<<64, 256>>>(W2, d_wh, d_wl);
    gemm_mma_kernel<true><<<GEMM_GRID, 256, SM_TOTAL>>>(d_agg, d_h);
    agg_stats_kernel<<<WARP_GRID, 256>>>(d_h, d_agg);
    bnparam_kernel<<<1, 128>>>(g2, be2);

    // --- layer 3 (BN fused GEMM; bias + L2norm fused into final agg) ---
    conv_w_kernel<<<64, 256>>>(W3, d_wh, d_wl);
    gemm_mma_kernel<true><<<GEMM_GRID, 256, SM_TOTAL>>>(d_agg, d_h);
    agg_final_kernel<<<WARP_GRID, 256>>>(d_h, b3, out);
}

// round 11
// speedup vs baseline: 1.9556x; 1.2554x over previous
#include <cuda_runtime.h>
#include <cuda_bf16.h>
#include <math.h>
#include <stdint.h>

#define NN 50000
#define EE 800000
#define DD 128
#define BN_EPS 1e-5f
#define NB 196          // ceil(NN/256) scan blocks

// ---------------- device scratch (no allocations allowed) ----------------
__device__ float g_h[(size_t)NN * DD];    // post-GEMM activations (fp32)
__device__ float g_agg[(size_t)NN * DD];  // aggregated
__device__ __nv_bfloat16 g_wh[3][DD * DD];  // per-layer W^T hi [n][k]
__device__ __nv_bfloat16 g_wl[3][DD * DD];  // per-layer W^T lo [n][k]
__device__ int   g_deg[NN];
__device__ float g_dinv[NN];
__device__ int   g_rowptr[NN + 1];
__device__ int   g_rowcur[NN];
__device__ int   g_col[EE];
__device__ float g_w[EE];                 // per-edge norm weight
__device__ int   g_bsum[256];
__device__ int   g_boff[256];
__device__ float g_sum[DD];
__device__ float g_sumsq[DD];
__device__ float g_scale[DD];
__device__ float g_shift[DD];
__device__ int   g_is64;

// ---------------- edge index access (int32 vs int64 tolerant) -----------
__device__ __forceinline__ int edge_src(const int* ei, int e) {
    return g_is64 ? ei[2 * e] : ei[e];
}
__device__ __forceinline__ int edge_dst(const int* ei, int e) {
    return g_is64 ? ei[2 * (EE + e)] : ei[EE + e];
}

// ---------------- graph preprocessing ----------------
// zero degrees + detect edge dtype + zero BN stats (one launch)
__global__ void init_kernel(const int* __restrict__ ei) {
    int i = blockIdx.x * blockDim.x + threadIdx.x;
    if (i < NN) g_deg[i] = 0;
    if (i < DD) { g_sum[i] = 0.0f; g_sumsq[i] = 0.0f; }
    if (i == 0) {
        // int64 values < 2^31 -> every odd int32 slot is 0.
        int is64 = 1;
        #pragma unroll
        for (int j = 1; j < 16; j += 2)
            if (ei[j] != 0) is64 = 0;
        g_is64 = is64;
    }
}

__global__ void deg_count_kernel(const int* __restrict__ ei) {
    int e = blockIdx.x * blockDim.x + threadIdx.x;
    if (e < EE) atomicAdd(&g_deg[edge_dst(ei, e)], 1);
}

__global__ __launch_bounds__(256) void blocksum_kernel() {
    int tid = threadIdx.x;
    int i = blockIdx.x * 256 + tid;
    int v = (i < NN) ? g_deg[i] : 0;
    #pragma unroll
    for (int off = 16; off; off >>= 1)
        v += __shfl_xor_sync(0xffffffffu, v, off);
    __shared__ int ws[8];
    if ((tid & 31) == 0) ws[tid >> 5] = v;
    __syncthreads();
    if (tid == 0) {
        int s = 0;
        #pragma unroll
        for (int w = 0; w < 8; w++) s += ws[w];
        g_bsum[blockIdx.x] = s;
    }
}

__global__ __launch_bounds__(256) void scan_bsums_kernel() {
    __shared__ int sm[256];
    int tid = threadIdx.x;
    int v = (tid < NB) ? g_bsum[tid] : 0;
    sm[tid] = v;
    __syncthreads();
    for (int off = 1; off < 256; off <<= 1) {
        int t = (tid >= off) ? sm[tid - off] : 0;
        __syncthreads();
        sm[tid] += t;
        __syncthreads();
    }
    if (tid < NB) g_boff[tid] = sm[tid] - v;       // exclusive
    if (tid == NB - 1) g_rowptr[NN] = sm[tid];     // total
}

__global__ __launch_bounds__(256) void scatter_scan_kernel() {
    __shared__ int sm[256];
    int tid = threadIdx.x;
    int i = blockIdx.x * 256 + tid;
    int d = (i < NN) ? g_deg[i] : 0;
    sm[tid] = d;
    __syncthreads();
    for (int off = 1; off < 256; off <<= 1) {
        int t = (tid >= off) ? sm[tid - off] : 0;
        __syncthreads();
        sm[tid] += t;
        __syncthreads();
    }
    if (i < NN) {
        int pos = g_boff[blockIdx.x] + sm[tid] - d;
        g_rowptr[i] = pos;
        g_rowcur[i] = pos;
        g_dinv[i] = rsqrtf((float)d + 1.0f);       // +1 self loop
    }
}

__global__ void fill_kernel(const int* __restrict__ ei) {
    int e = blockIdx.x * blockDim.x + threadIdx.x;
    if (e < EE) {
        int d = edge_dst(ei, e);
        int s = edge_src(ei, e);
        int pos = atomicAdd(&g_rowcur[d], 1);
        g_col[pos] = s;
        g_w[pos] = g_dinv[s] * g_dinv[d];
    }
}

// W[k][n] -> W^T hi/lo [n][k]
__global__ void conv_w_kernel(const float* __restrict__ W,
                              __nv_bfloat16* __restrict__ wh,
                              __nv_bfloat16* __restrict__ wl)
{
    int i = blockIdx.x * 256 + threadIdx.x;
    if (i >= DD * DD) return;
    int n = i >> 7, k = i & 127;
    float v = W[k * DD + n];
    __nv_bfloat16 h = __float2bfloat16(v);
    __nv_bfloat16 l = __float2bfloat16(v - __bfloat162float(h));
    wh[i] = h;
    wl[i] = l;
}

// ---------------- HMMA GEMM: h[M,128] = act(A)[M,128] @ W[128,128] -----
// mma.sync m16n8k16 bf16 + ldmatrix. Split precision Ah@Wh + Ah@Wl + Al@Wh,
// fp32 accumulate. BN+ReLU+hi/lo-split fused into the A-tile smem load.
// K processed in two 64-wide chunks -> smem 72KB -> occupancy 2 (load of
// one block overlaps compute of the other).
// CTA tile 128x128, 8 warps = 4(M) x 2(N), each warp 32x64.

#define PITCH 72
#define KC 64
#define TILEB (128 * PITCH * 2)   // 18432
#define SM_AHI 0
#define SM_ALO TILEB
#define SM_WHI (2 * TILEB)
#define SM_WLO (3 * TILEB)
#define SM_TOTAL (4 * TILEB)      // 73728

static __device__ __forceinline__ uint32_t smem_u32(const void* p) {
    uint32_t a;
    asm("{ .reg .u64 t; cvta.to.shared.u64 t, %1; cvt.u32.u64 %0, t; }"
        : "=r"(a) : "l"(p));
    return a;
}

__device__ __forceinline__ void ldm_x4(uint32_t* r, uint32_t addr) {
    asm volatile("ldmatrix.sync.aligned.m8n8.x4.shared.b16 {%0,%1,%2,%3}, [%4];"
                 : "=r"(r[0]), "=r"(r[1]), "=r"(r[2]), "=r"(r[3]) : "r"(addr));
}

__device__ __forceinline__ void mma16816(float* d, const uint32_t* a,
                                         uint32_t b0, uint32_t b1) {
    asm volatile(
        "mma.sync.aligned.m16n8k16.row.col.f32.bf16.bf16.f32 "
        "{%0,%1,%2,%3}, {%4,%5,%6,%7}, {%8,%9}, {%0,%1,%2,%3};"
        : "+f"(d[0]), "+f"(d[1]), "+f"(d[2]), "+f"(d[3])
        : "r"(a[0]), "r"(a[1]), "r"(a[2]), "r"(a[3]), "r"(b0), "r"(b1));
}

template<bool BN>
__global__ __launch_bounds__(256, 2)
void gemm_mma_kernel(const float* __restrict__ A,
                     const __nv_bfloat16* __restrict__ Wh,
                     const __nv_bfloat16* __restrict__ Wl,
                     float* __restrict__ C)
{
    extern __shared__ char smem[];
    uint32_t sbase = smem_u32(smem);
    int tid = threadIdx.x;
    int wid = tid >> 5;
    int lane = tid & 31;
    int m0blk = blockIdx.x * 128;
    int wm = (wid & 3) * 32;        // warp M offset in tile
    int wn = (wid >> 2) * 64;       // warp N offset in tile

    float acc[2][8][4];
    #pragma unroll
    for (int mt = 0; mt < 2; mt++)
        #pragma unroll
        for (int nt = 0; nt < 8; nt++)
            #pragma unroll
            for (int q = 0; q < 4; q++) acc[mt][nt][q] = 0.0f;

    // ldmatrix lane address components
    int a_row = (lane & 7) + 8 * ((lane >> 3) & 1);
    int a_kof = 8 * (lane >> 4);
    int b_nof = (lane & 7) + 8 * (lane >> 4);
    int b_kof = 8 * ((lane >> 3) & 1);

    #pragma unroll
    for (int kc = 0; kc < 2; kc++) {
        int kbase = kc * KC;
        if (kc) __syncthreads();    // protect previous chunk's tiles

        // A chunk (128 rows x 64 cols fp32) with fused BN+ReLU+split
        for (int idx = tid; idx < 2048; idx += 256) {
            int r = idx >> 4;
            int c4 = (idx & 15) * 4;      // col within chunk
            int gc = kbase + c4;
            float4 v = make_float4(0.f, 0.f, 0.f, 0.f);
            if (m0blk + r < NN)
                v = *(const float4*)(A + (size_t)(m0blk + r) * DD + gc);
            if (BN) {
                v.x = fmaxf(fmaf(v.x, g_scale[gc + 0], g_shift[gc + 0]), 0.0f);
                v.y = fmaxf(fmaf(v.y, g_scale[gc + 1], g_shift[gc + 1]), 0.0f);
                v.z = fmaxf(fmaf(v.z, g_scale[gc + 2], g_shift[gc + 2]), 0.0f);
                v.w = fmaxf(fmaf(v.w, g_scale[gc + 3], g_shift[gc + 3]), 0.0f);
            }
            float a[4] = {v.x, v.y, v.z, v.w};
            uint32_t ph[2], pl[2];
            #pragma unroll
            for (int p = 0; p < 2; p++) {
                __nv_bfloat16 h0 = __float2bfloat16(a[2 * p]);
                __nv_bfloat16 h1 = __float2bfloat16(a[2 * p + 1]);
                __nv_bfloat16 l0 = __float2bfloat16(a[2 * p] - __bfloat162float(h0));
                __nv_bfloat16 l1 = __float2bfloat16(a[2 * p + 1] - __bfloat162float(h1));
                ph[p] = (uint32_t)__bfloat16_as_ushort(h0) | ((uint32_t)__bfloat16_as_ushort(h1) << 16);
                pl[p] = (uint32_t)__bfloat16_as_ushort(l0) | ((uint32_t)__bfloat16_as_ushort(l1) << 16);
            }
            size_t boff = ((size_t)r * PITCH + c4) * 2;
            *(uint2*)(smem + SM_AHI + boff) = make_uint2(ph[0], ph[1]);
            *(uint2*)(smem + SM_ALO + boff) = make_uint2(pl[0], pl[1]);
        }
        // W chunk (128 n-rows x 64 k) hi+lo: 1024 x 16B each
        for (int idx = tid; idx < 1024; idx += 256) {
            int n = idx >> 3;
            int kq = (idx & 7) * 8;
            uint4 vh = *(const uint4*)(Wh + (size_t)n * DD + kbase + kq);
            uint4 vl = *(const uint4*)(Wl + (size_t)n * DD + kbase + kq);
            size_t boff = ((size_t)n * PITCH + kq) * 2;
            *(uint4*)(smem + SM_WHI + boff) = vh;
            *(uint4*)(smem + SM_WLO + boff) = vl;
        }
        __syncthreads();

        #pragma unroll
        for (int k0 = 0; k0 < KC; k0 += 16) {
            uint32_t aH[2][4], aL[2][4];
            #pragma unroll
            for (int mt = 0; mt < 2; mt++) {
                uint32_t ad = sbase + SM_AHI
                    + ((uint32_t)(wm + mt * 16 + a_row) * PITCH + k0 + a_kof) * 2;
                ldm_x4(aH[mt], ad);
                ldm_x4(aL[mt], ad + (SM_ALO - SM_AHI));
            }
            #pragma unroll
            for (int ng = 0; ng < 4; ng++) {
                uint32_t bH[4], bL[4];
                uint32_t bd = sbase + SM_WHI
                    + ((uint32_t)(wn + ng * 16 + b_nof) * PITCH + k0 + b_kof) * 2;
                ldm_x4(bH, bd);
                ldm_x4(bL, bd + (SM_WLO - SM_WHI));
                #pragma unroll
                for (int mt = 0; mt < 2; mt++)
                    #pragma unroll
                    for (int half = 0; half < 2; half++) {
                        int nt = ng * 2 + half;
                        int s = half * 2;
                        mma16816(acc[mt][nt], aH[mt], bH[s], bH[s + 1]);
                        mma16816(acc[mt][nt], aH[mt], bL[s], bL[s + 1]);
                        mma16816(acc[mt][nt], aL[mt], bH[s], bH[s + 1]);
                    }
            }
        }
    }

    // store accumulators
    #pragma unroll
    for (int mt = 0; mt < 2; mt++) {
        int row0 = m0blk + wm + mt * 16 + (lane >> 2);
        int row1 = row0 + 8;
        #pragma unroll
        for (int nt = 0; nt < 8; nt++) {
            int col = wn + nt * 8 + (lane & 3) * 2;
            if (row0 < NN)
                *(float2*)(C + (size_t)row0 * DD + col) =
                    make_float2(acc[mt][nt][0], acc[mt][nt][1]);
            if (row1 < NN)
                *(float2*)(C + (size_t)row1 * DD + col) =
                    make_float2(acc[mt][nt][2], acc[mt][nt][3]);
        }
    }
}

// ---------------- aggregation + fused BN statistics ----------------------
__global__ __launch_bounds__(256) void agg_stats_kernel(
    const float* __restrict__ h, float* __restrict__ out)
{
    __shared__ float ssum[DD];
    __shared__ float ssq[DD];
    int tid = threadIdx.x;
    if (tid < DD) { ssum[tid] = 0.0f; ssq[tid] = 0.0f; }
    __syncthreads();

    int gw = (blockIdx.x * blockDim.x + tid) >> 5;
    int lane = tid & 31;

    if (gw < NN) {
        float di = g_dinv[gw];
        float4 acc = *(const float4*)(h + (size_t)gw * DD + lane * 4);
        float wself = di * di;
        acc.x *= wself; acc.y *= wself; acc.z *= wself; acc.w *= wself;

        int beg = g_rowptr[gw];
        int end = g_rowptr[gw + 1];
        int e = beg;
        for (; e + 3 < end; e += 4) {
            int s0 = g_col[e], s1 = g_col[e + 1], s2 = g_col[e + 2], s3 = g_col[e + 3];
            float w0 = g_w[e], w1 = g_w[e + 1], w2 = g_w[e + 2], w3 = g_w[e + 3];
            float4 v0 = *(const float4*)(h + (size_t)s0 * DD + lane * 4);
            float4 v1 = *(const float4*)(h + (size_t)s1 * DD + lane * 4);
            float4 v2 = *(const float4*)(h + (size_t)s2 * DD + lane * 4);
            float4 v3 = *(const float4*)(h + (size_t)s3 * DD + lane * 4);
            acc.x = fmaf(v0.x, w0, acc.x); acc.y = fmaf(v0.y, w0, acc.y);
            acc.z = fmaf(v0.z, w0, acc.z); acc.w = fmaf(v0.w, w0, acc.w);
            acc.x = fmaf(v1.x, w1, acc.x); acc.y = fmaf(v1.y, w1, acc.y);
            acc.z = fmaf(v1.z, w1, acc.z); acc.w = fmaf(v1.w, w1, acc.w);
            acc.x = fmaf(v2.x, w2, acc.x); acc.y = fmaf(v2.y, w2, acc.y);
            acc.z = fmaf(v2.z, w2, acc.z); acc.w = fmaf(v2.w, w2, acc.w);
            acc.x = fmaf(v3.x, w3, acc.x); acc.y = fmaf(v3.y, w3, acc.y);
            acc.z = fmaf(v3.z, w3, acc.z); acc.w = fmaf(v3.w, w3, acc.w);
        }
        for (; e < end; e++) {
            int s = g_col[e];
            float w = g_w[e];
            float4 v = *(const float4*)(h + (size_t)s * DD + lane * 4);
            acc.x = fmaf(v.x, w, acc.x); acc.y = fmaf(v.y, w, acc.y);
            acc.z = fmaf(v.z, w, acc.z); acc.w = fmaf(v.w, w, acc.w);
        }
        *(float4*)(out + (size_t)gw * DD + lane * 4) = acc;

        int f = lane * 4;
        atomicAdd(&ssum[f + 0], acc.x);
        atomicAdd(&ssum[f + 1], acc.y);
        atomicAdd(&ssum[f + 2], acc.z);
        atomicAdd(&ssum[f + 3], acc.w);
        atomicAdd(&ssq[f + 0], acc.x * acc.x);
        atomicAdd(&ssq[f + 1], acc.y * acc.y);
        atomicAdd(&ssq[f + 2], acc.z * acc.z);
        atomicAdd(&ssq[f + 3], acc.w * acc.w);
    }
    __syncthreads();
    if (tid < DD) {
        atomicAdd(&g_sum[tid], ssum[tid]);
        atomicAdd(&g_sumsq[tid], ssq[tid]);
    }
}

// ---------------- final aggregation + bias + L2 normalize ----------------
__global__ __launch_bounds__(256) void agg_final_kernel(
    const float* __restrict__ h, const float* __restrict__ b3,
    float* __restrict__ out)
{
    int gw = (blockIdx.x * blockDim.x + threadIdx.x) >> 5;
    int lane = threadIdx.x & 31;
    if (gw >= NN) return;

    float di = g_dinv[gw];
    float4 acc = *(const float4*)(h + (size_t)gw * DD + lane * 4);
    float wself = di * di;
    acc.x *= wself; acc.y *= wself; acc.z *= wself; acc.w *= wself;

    int beg = g_rowptr[gw];
    int end = g_rowptr[gw + 1];
    int e = beg;
    for (; e + 3 < end; e += 4) {
        int s0 = g_col[e], s1 = g_col[e + 1], s2 = g_col[e + 2], s3 = g_col[e + 3];
        float w0 = g_w[e], w1 = g_w[e + 1], w2 = g_w[e + 2], w3 = g_w[e + 3];
        float4 v0 = *(const float4*)(h + (size_t)s0 * DD + lane * 4);
        float4 v1 = *(const float4*)(h + (size_t)s1 * DD + lane * 4);
        float4 v2 = *(const float4*)(h + (size_t)s2 * DD + lane * 4);
        float4 v3 = *(const float4*)(h + (size_t)s3 * DD + lane * 4);
        acc.x = fmaf(v0.x, w0, acc.x); acc.y = fmaf(v0.y, w0, acc.y);
        acc.z = fmaf(v0.z, w0, acc.z); acc.w = fmaf(v0.w, w0, acc.w);
        acc.x = fmaf(v1.x, w1, acc.x); acc.y = fmaf(v1.y, w1, acc.y);
        acc.z = fmaf(v1.z, w1, acc.z); acc.w = fmaf(v1.w, w1, acc.w);
        acc.x = fmaf(v2.x, w2, acc.x); acc.y = fmaf(v2.y, w2, acc.y);
        acc.z = fmaf(v2.z, w2, acc.z); acc.w = fmaf(v2.w, w2, acc.w);
        acc.x = fmaf(v3.x, w3, acc.x); acc.y = fmaf(v3.y, w3, acc.y);
        acc.z = fmaf(v3.z, w3, acc.z); acc.w = fmaf(v3.w, w3, acc.w);
    }
    for (; e < end; e++) {
        int s = g_col[e];
        float w = g_w[e];
        float4 v = *(const float4*)(h + (size_t)s * DD + lane * 4);
        acc.x = fmaf(v.x, w, acc.x); acc.y = fmaf(v.y, w, acc.y);
        acc.z = fmaf(v.z, w, acc.z); acc.w = fmaf(v.w, w, acc.w);
    }

    float4 bb = ((const float4*)b3)[lane];
    acc.x += bb.x; acc.y += bb.y; acc.z += bb.z; acc.w += bb.w;
    float ss = acc.x * acc.x + acc.y * acc.y + acc.z * acc.z + acc.w * acc.w;
    #pragma unroll
    for (int off = 16; off; off >>= 1)
        ss += __shfl_xor_sync(0xffffffffu, ss, off);
    float inv = 1.0f / fmaxf(sqrtf(ss), 1e-12f);
    float4 o = make_float4(acc.x * inv, acc.y * inv, acc.z * inv, acc.w * inv);
    *(float4*)(out + (size_t)gw * DD + lane * 4) = o;
}

// ---------------- BatchNorm params (consumes + re-zeroes stats) ----------
__global__ void bnparam_kernel(const float* __restrict__ g, const float* __restrict__ be) {
    int f = threadIdx.x;
    if (f < DD) {
        float mu = g_sum[f] * (1.0f / NN);
        float var = g_sumsq[f] * (1.0f / NN) - mu * mu;
        float sc = g[f] * rsqrtf(var + BN_EPS);
        g_scale[f] = sc;
        g_shift[f] = be[f] - mu * sc;
        g_sum[f] = 0.0f;       // ready for next layer's agg_stats
        g_sumsq[f] = 0.0f;
    }
}

// ---------------- launch ----------------
extern "C" void kernel_launch(void* const* d_in, const int* in_sizes, int n_in,
                              void* d_out, int out_size)
{
    const float* x   = (const float*)d_in[0];
    const int*   ei  = (const int*)d_in[1];
    const float* W1  = (const float*)d_in[2];
    // b1 = d_in[3]  -- no-op before BatchNorm
    const float* W2  = (const float*)d_in[4];
    // b2 = d_in[5]  -- no-op before BatchNorm
    const float* W3  = (const float*)d_in[6];
    const float* b3  = (const float*)d_in[7];
    const float* g1  = (const float*)d_in[8];
    const float* be1 = (const float*)d_in[9];
    const float* g2  = (const float*)d_in[10];
    const float* be2 = (const float*)d_in[11];
    float* out = (float*)d_out;

    float* d_h;   cudaGetSymbolAddress((void**)&d_h,   g_h);
    float* d_agg; cudaGetSymbolAddress((void**)&d_agg, g_agg);
    __nv_bfloat16* d_wh; cudaGetSymbolAddress((void**)&d_wh, g_wh);
    __nv_bfloat16* d_wl; cudaGetSymbolAddress((void**)&d_wl, g_wl);
    __nv_bfloat16* wh1 = d_wh,           *wl1 = d_wl;
    __nv_bfloat16* wh2 = d_wh + DD * DD, *wl2 = d_wl + DD * DD;
    __nv_bfloat16* wh3 = d_wh + 2 * DD * DD, *wl3 = d_wl + 2 * DD * DD;

    static cudaStream_t sB = nullptr, sC = nullptr;
    static cudaEvent_t e0 = nullptr, eB = nullptr, eC = nullptr;
    if (!sB) {
        cudaStreamCreateWithFlags(&sB, cudaStreamNonBlocking);
        cudaStreamCreateWithFlags(&sC, cudaStreamNonBlocking);
        cudaEventCreateWithFlags(&e0, cudaEventDisableTiming);
        cudaEventCreateWithFlags(&eB, cudaEventDisableTiming);
        cudaEventCreateWithFlags(&eC, cudaEventDisableTiming);
        cudaFuncSetAttribute(gemm_mma_kernel<false>,
                             cudaFuncAttributeMaxDynamicSharedMemorySize, SM_TOTAL);
        cudaFuncSetAttribute(gemm_mma_kernel<true>,
                             cudaFuncAttributeMaxDynamicSharedMemorySize, SM_TOTAL);
    }

    const int GEMM_GRID = (NN + 127) / 128;   // 391
    const int WARP_GRID = NN / 8;             // 6250

    // ---- fork: preprocessing on sB, layer-2/3 weight conversion on sC ----
    cudaEventRecord(e0, 0);
    cudaStreamWaitEvent(sB, e0, 0);
    cudaStreamWaitEvent(sC, e0, 0);

    init_kernel<<<(NN + 255) / 256, 256, 0, sB>>>(ei);
    deg_count_kernel<<<(EE + 255) / 256, 256, 0, sB>>>(ei);
    blocksum_kernel<<<NB, 256, 0, sB>>>();
    scan_bsums_kernel<<<1, 256, 0, sB>>>();
    scatter_scan_kernel<<<NB, 256, 0, sB>>>();
    fill_kernel<<<(EE + 255) / 256, 256, 0, sB>>>(ei);
    cudaEventRecord(eB, sB);

    conv_w_kernel<<<64, 256, 0, sC>>>(W2, wh2, wl2);
    conv_w_kernel<<<64, 256, 0, sC>>>(W3, wh3, wl3);
    cudaEventRecord(eC, sC);

    // ---- main stream: layer 1 GEMM overlaps preprocessing ----
    conv_w_kernel<<<64, 256>>>(W1, wh1, wl1);
    gemm_mma_kernel<false><<<GEMM_GRID, 256, SM_TOTAL>>>(x, wh1, wl1, d_h);

    cudaStreamWaitEvent(0, eB, 0);   // CSR + stats-zero ready
    agg_stats_kernel<<<WARP_GRID, 256>>>(d_h, d_agg);
    bnparam_kernel<<<1, 128>>>(g1, be1);

    // ---- layer 2 ----
    cudaStreamWaitEvent(0, eC, 0);   // W2/W3 conversions ready
    gemm_mma_kernel<true><<<GEMM_GRID, 256, SM_TOTAL>>>(d_agg, wh2, wl2, d_h);
    agg_stats_kernel<<<WARP_GRID, 256>>>(d_h, d_agg);
    bnparam_kernel<<<1, 128>>>(g2, be2);

    // ---- layer 3 ----
    gemm_mma_kernel<true><<<GEMM_GRID, 256, SM_TOTAL>>>(d_agg, wh3, wl3, d_h);
    agg_final_kernel<<<WARP_GRID, 256>>>(d_h, b3, out);
}

// round 12
// speedup vs baseline: 2.4301x; 1.2426x over previous
#include <cuda_runtime.h>
#include <cuda_bf16.h>
#include <cuda_fp16.h>
#include <math.h>
#include <stdint.h>

#define NN 50000
#define EE 800000
#define DD 128
#define BN_EPS 1e-5f
#define NB 196          // ceil(NN/256) scan blocks

// ---------------- device scratch (no allocations allowed) ----------------
__device__ __half g_h[(size_t)NN * DD];   // post-GEMM activations (fp16!)
__device__ float g_agg[(size_t)NN * DD];  // aggregated (fp32)
__device__ __nv_bfloat16 g_wh[3][DD * DD];  // per-layer W^T hi [n][k]
__device__ __nv_bfloat16 g_wl[3][DD * DD];  // per-layer W^T lo [n][k]
__device__ int   g_deg[NN];
__device__ float g_dinv[NN];
__device__ int   g_rowptr[NN + 1];
__device__ int   g_rowcur[NN];
__device__ int   g_col[EE];
__device__ float g_w[EE];                 // per-edge norm weight
__device__ int   g_bsum[256];
__device__ int   g_boff[256];
__device__ float g_sum[2][DD];            // double-buffered BN stats
__device__ float g_sumsq[2][DD];
__device__ int   g_is64;

// ---------------- edge index access (int32 vs int64 tolerant) -----------
__device__ __forceinline__ int edge_src(const int* ei, int e) {
    return g_is64 ? ei[2 * e] : ei[e];
}
__device__ __forceinline__ int edge_dst(const int* ei, int e) {
    return g_is64 ? ei[2 * (EE + e)] : ei[EE + e];
}

// ---------------- graph preprocessing ----------------
// zero degrees + detect edge dtype + zero BN stats (one launch)
__global__ void init_kernel(const int* __restrict__ ei) {
    int i = blockIdx.x * blockDim.x + threadIdx.x;
    if (i < NN) g_deg[i] = 0;
    if (i < DD) {
        g_sum[0][i] = 0.0f; g_sumsq[0][i] = 0.0f;
        g_sum[1][i] = 0.0f; g_sumsq[1][i] = 0.0f;
    }
    if (i == 0) {
        // int64 values < 2^31 -> every odd int32 slot is 0.
        int is64 = 1;
        #pragma unroll
        for (int j = 1; j < 16; j += 2)
            if (ei[j] != 0) is64 = 0;
        g_is64 = is64;
    }
}

__global__ void deg_count_kernel(const int* __restrict__ ei) {
    int e = blockIdx.x * blockDim.x + threadIdx.x;
    if (e < EE) atomicAdd(&g_deg[edge_dst(ei, e)], 1);
}

__global__ __launch_bounds__(256) void blocksum_kernel() {
    int tid = threadIdx.x;
    int i = blockIdx.x * 256 + tid;
    int v = (i < NN) ? g_deg[i] : 0;
    #pragma unroll
    for (int off = 16; off; off >>= 1)
        v += __shfl_xor_sync(0xffffffffu, v, off);
    __shared__ int ws[8];
    if ((tid & 31) == 0) ws[tid >> 5] = v;
    __syncthreads();
    if (tid == 0) {
        int s = 0;
        #pragma unroll
        for (int w = 0; w < 8; w++) s += ws[w];
        g_bsum[blockIdx.x] = s;
    }
}

__global__ __launch_bounds__(256) void scan_bsums_kernel() {
    __shared__ int sm[256];
    int tid = threadIdx.x;
    int v = (tid < NB) ? g_bsum[tid] : 0;
    sm[tid] = v;
    __syncthreads();
    for (int off = 1; off < 256; off <<= 1) {
        int t = (tid >= off) ? sm[tid - off] : 0;
        __syncthreads();
        sm[tid] += t;
        __syncthreads();
    }
    if (tid < NB) g_boff[tid] = sm[tid] - v;       // exclusive
    if (tid == NB - 1) g_rowptr[NN] = sm[tid];     // total
}

__global__ __launch_bounds__(256) void scatter_scan_kernel() {
    __shared__ int sm[256];
    int tid = threadIdx.x;
    int i = blockIdx.x * 256 + tid;
    int d = (i < NN) ? g_deg[i] : 0;
    sm[tid] = d;
    __syncthreads();
    for (int off = 1; off < 256; off <<= 1) {
        int t = (tid >= off) ? sm[tid - off] : 0;
        __syncthreads();
        sm[tid] += t;
        __syncthreads();
    }
    if (i < NN) {
        int pos = g_boff[blockIdx.x] + sm[tid] - d;
        g_rowptr[i] = pos;
        g_rowcur[i] = pos;
        g_dinv[i] = rsqrtf((float)d + 1.0f);       // +1 self loop
    }
}

__global__ void fill_kernel(const int* __restrict__ ei) {
    int e = blockIdx.x * blockDim.x + threadIdx.x;
    if (e < EE) {
        int d = edge_dst(ei, e);
        int s = edge_src(ei, e);
        int pos = atomicAdd(&g_rowcur[d], 1);
        g_col[pos] = s;
        g_w[pos] = g_dinv[s] * g_dinv[d];
    }
}

// W[k][n] -> W^T hi/lo [n][k]
__global__ void conv_w_kernel(const float* __restrict__ W,
                              __nv_bfloat16* __restrict__ wh,
                              __nv_bfloat16* __restrict__ wl)
{
    int i = blockIdx.x * 256 + threadIdx.x;
    if (i >= DD * DD) return;
    int n = i >> 7, k = i & 127;
    float v = W[k * DD + n];
    __nv_bfloat16 h = __float2bfloat16(v);
    __nv_bfloat16 l = __float2bfloat16(v - __bfloat162float(h));
    wh[i] = h;
    wl[i] = l;
}

// ---------------- HMMA GEMM: h[M,128] = act(A)[M,128] @ W[128,128] -----
// mma.sync m16n8k16 bf16 + ldmatrix. Split precision Ah@Wh + Ah@Wl + Al@Wh,
// fp32 accumulate. BN params computed in-block from double-buffered stats
// (bnparam kernel folded in); BN+ReLU+hi/lo-split fused into A-tile load.
// Output written fp16 (only consumer is the aggregation gather).
// K in two 64-chunks -> 72KB smem -> occupancy 2.
// CTA tile 128x128, 8 warps = 4(M) x 2(N), each warp 32x64.

#define PITCH 72
#define KC 64
#define TILEB (128 * PITCH * 2)   // 18432
#define SM_AHI 0
#define SM_ALO TILEB
#define SM_WHI (2 * TILEB)
#define SM_WLO (3 * TILEB)
#define SM_TOTAL (4 * TILEB)      // 73728

static __device__ __forceinline__ uint32_t smem_u32(const void* p) {
    uint32_t a;
    asm("{ .reg .u64 t; cvta.to.shared.u64 t, %1; cvt.u32.u64 %0, t; }"
        : "=r"(a) : "l"(p));
    return a;
}

__device__ __forceinline__ void ldm_x4(uint32_t* r, uint32_t addr) {
    asm volatile("ldmatrix.sync.aligned.m8n8.x4.shared.b16 {%0,%1,%2,%3}, [%4];"
                 : "=r"(r[0]), "=r"(r[1]), "=r"(r[2]), "=r"(r[3]) : "r"(addr));
}

__device__ __forceinline__ void mma16816(float* d, const uint32_t* a,
                                         uint32_t b0, uint32_t b1) {
    asm volatile(
        "mma.sync.aligned.m16n8k16.row.col.f32.bf16.bf16.f32 "
        "{%0,%1,%2,%3}, {%4,%5,%6,%7}, {%8,%9}, {%0,%1,%2,%3};"
        : "+f"(d[0]), "+f"(d[1]), "+f"(d[2]), "+f"(d[3])
        : "r"(a[0]), "r"(a[1]), "r"(a[2]), "r"(a[3]), "r"(b0), "r"(b1));
}

template<bool BN>
__global__ __launch_bounds__(256, 2)
void gemm_mma_kernel(const float* __restrict__ A,
                     const __nv_bfloat16* __restrict__ Wh,
                     const __nv_bfloat16* __restrict__ Wl,
                     const float* __restrict__ gamma,
                     const float* __restrict__ beta,
                     const float* __restrict__ gsum,
                     const float* __restrict__ gsq,
                     __half* __restrict__ C)
{
    extern __shared__ char smem[];
    __shared__ float s_scale[DD];
    __shared__ float s_shift[DD];
    uint32_t sbase = smem_u32(smem);
    int tid = threadIdx.x;
    int wid = tid >> 5;
    int lane = tid & 31;
    int m0blk = blockIdx.x * 128;
    int wm = (wid & 3) * 32;        // warp M offset in tile
    int wn = (wid >> 2) * 64;       // warp N offset in tile

    if (BN && tid < DD) {
        float mu = gsum[tid] * (1.0f / NN);
        float var = gsq[tid] * (1.0f / NN) - mu * mu;
        float sc = gamma[tid] * rsqrtf(var + BN_EPS);
        s_scale[tid] = sc;
        s_shift[tid] = beta[tid] - mu * sc;
    }
    if (BN) __syncthreads();

    float acc[2][8][4];
    #pragma unroll
    for (int mt = 0; mt < 2; mt++)
        #pragma unroll
        for (int nt = 0; nt < 8; nt++)
            #pragma unroll
            for (int q = 0; q < 4; q++) acc[mt][nt][q] = 0.0f;

    // ldmatrix lane address components
    int a_row = (lane & 7) + 8 * ((lane >> 3) & 1);
    int a_kof = 8 * (lane >> 4);
    int b_nof = (lane & 7) + 8 * (lane >> 4);
    int b_kof = 8 * ((lane >> 3) & 1);

    #pragma unroll
    for (int kc = 0; kc < 2; kc++) {
        int kbase = kc * KC;
        if (kc) __syncthreads();    // protect previous chunk's tiles

        // A chunk (128 rows x 64 cols fp32) with fused BN+ReLU+split
        for (int idx = tid; idx < 2048; idx += 256) {
            int r = idx >> 4;
            int c4 = (idx & 15) * 4;      // col within chunk
            int gc = kbase + c4;
            float4 v = make_float4(0.f, 0.f, 0.f, 0.f);
            if (m0blk + r < NN)
                v = *(const float4*)(A + (size_t)(m0blk + r) * DD + gc);
            if (BN) {
                v.x = fmaxf(fmaf(v.x, s_scale[gc + 0], s_shift[gc + 0]), 0.0f);
                v.y = fmaxf(fmaf(v.y, s_scale[gc + 1], s_shift[gc + 1]), 0.0f);
                v.z = fmaxf(fmaf(v.z, s_scale[gc + 2], s_shift[gc + 2]), 0.0f);
                v.w = fmaxf(fmaf(v.w, s_scale[gc + 3], s_shift[gc + 3]), 0.0f);
            }
            float a[4] = {v.x, v.y, v.z, v.w};
            uint32_t ph[2], pl[2];
            #pragma unroll
            for (int p = 0; p < 2; p++) {
                __nv_bfloat16 h0 = __float2bfloat16(a[2 * p]);
                __nv_bfloat16 h1 = __float2bfloat16(a[2 * p + 1]);
                __nv_bfloat16 l0 = __float2bfloat16(a[2 * p] - __bfloat162float(h0));
                __nv_bfloat16 l1 = __float2bfloat16(a[2 * p + 1] - __bfloat162float(h1));
                ph[p] = (uint32_t)__bfloat16_as_ushort(h0) | ((uint32_t)__bfloat16_as_ushort(h1) << 16);
                pl[p] = (uint32_t)__bfloat16_as_ushort(l0) | ((uint32_t)__bfloat16_as_ushort(l1) << 16);
            }
            size_t boff = ((size_t)r * PITCH + c4) * 2;
            *(uint2*)(smem + SM_AHI + boff) = make_uint2(ph[0], ph[1]);
            *(uint2*)(smem + SM_ALO + boff) = make_uint2(pl[0], pl[1]);
        }
        // W chunk (128 n-rows x 64 k) hi+lo: 1024 x 16B each
        for (int idx = tid; idx < 1024; idx += 256) {
            int n = idx >> 3;
            int kq = (idx & 7) * 8;
            uint4 vh = *(const uint4*)(Wh + (size_t)n * DD + kbase + kq);
            uint4 vl = *(const uint4*)(Wl + (size_t)n * DD + kbase + kq);
            size_t boff = ((size_t)n * PITCH + kq) * 2;
            *(uint4*)(smem + SM_WHI + boff) = vh;
            *(uint4*)(smem + SM_WLO + boff) = vl;
        }
        __syncthreads();

        #pragma unroll
        for (int k0 = 0; k0 < KC; k0 += 16) {
            uint32_t aH[2][4], aL[2][4];
            #pragma unroll
            for (int mt = 0; mt < 2; mt++) {
                uint32_t ad = sbase + SM_AHI
                    + ((uint32_t)(wm + mt * 16 + a_row) * PITCH + k0 + a_kof) * 2;
                ldm_x4(aH[mt], ad);
                ldm_x4(aL[mt], ad + (SM_ALO - SM_AHI));
            }
            #pragma unroll
            for (int ng = 0; ng < 4; ng++) {
                uint32_t bH[4], bL[4];
                uint32_t bd = sbase + SM_WHI
                    + ((uint32_t)(wn + ng * 16 + b_nof) * PITCH + k0 + b_kof) * 2;
                ldm_x4(bH, bd);
                ldm_x4(bL, bd + (SM_WLO - SM_WHI));
                #pragma unroll
                for (int mt = 0; mt < 2; mt++)
                    #pragma unroll
                    for (int half = 0; half < 2; half++) {
                        int nt = ng * 2 + half;
                        int s = half * 2;
                        mma16816(acc[mt][nt], aH[mt], bH[s], bH[s + 1]);
                        mma16816(acc[mt][nt], aH[mt], bL[s], bL[s + 1]);
                        mma16816(acc[mt][nt], aL[mt], bH[s], bH[s + 1]);
                    }
            }
        }
    }

    // store accumulators as fp16
    #pragma unroll
    for (int mt = 0; mt < 2; mt++) {
        int row0 = m0blk + wm + mt * 16 + (lane >> 2);
        int row1 = row0 + 8;
        #pragma unroll
        for (int nt = 0; nt < 8; nt++) {
            int col = wn + nt * 8 + (lane & 3) * 2;
            if (row0 < NN)
                *(__half2*)(C + (size_t)row0 * DD + col) =
                    __floats2half2_rn(acc[mt][nt][0], acc[mt][nt][1]);
            if (row1 < NN)
                *(__half2*)(C + (size_t)row1 * DD + col) =
                    __floats2half2_rn(acc[mt][nt][2], acc[mt][nt][3]);
        }
    }
}

// ---------------- fp16 gather helper ----------------
__device__ __forceinline__ void acc_edge(float4& acc, const __half* __restrict__ h,
                                         int s, int lane, float w)
{
    uint2 raw = *(const uint2*)(h + (size_t)s * DD + lane * 4);
    float2 f0 = __half22float2(*(__half2*)&raw.x);
    float2 f1 = __half22float2(*(__half2*)&raw.y);
    acc.x = fmaf(f0.x, w, acc.x);
    acc.y = fmaf(f0.y, w, acc.y);
    acc.z = fmaf(f1.x, w, acc.z);
    acc.w = fmaf(f1.y, w, acc.w);
}

// ---------------- aggregation + fused BN statistics ----------------------
__global__ __launch_bounds__(256) void agg_stats_kernel(
    const __half* __restrict__ h, float* __restrict__ out,
    float* __restrict__ gsum, float* __restrict__ gsq)
{
    __shared__ float ssum[DD];
    __shared__ float ssq[DD];
    int tid = threadIdx.x;
    if (tid < DD) { ssum[tid] = 0.0f; ssq[tid] = 0.0f; }
    __syncthreads();

    int gw = (blockIdx.x * blockDim.x + tid) >> 5;
    int lane = tid & 31;

    if (gw < NN) {
        float di = g_dinv[gw];
        float4 acc = make_float4(0.f, 0.f, 0.f, 0.f);
        acc_edge(acc, h, gw, lane, di * di);   // self loop

        int beg = g_rowptr[gw];
        int end = g_rowptr[gw + 1];
        int e = beg;
        for (; e + 3 < end; e += 4) {
            int s0 = g_col[e], s1 = g_col[e + 1], s2 = g_col[e + 2], s3 = g_col[e + 3];
            float w0 = g_w[e], w1 = g_w[e + 1], w2 = g_w[e + 2], w3 = g_w[e + 3];
            acc_edge(acc, h, s0, lane, w0);
            acc_edge(acc, h, s1, lane, w1);
            acc_edge(acc, h, s2, lane, w2);
            acc_edge(acc, h, s3, lane, w3);
        }
        for (; e < end; e++)
            acc_edge(acc, h, g_col[e], lane, g_w[e]);

        *(float4*)(out + (size_t)gw * DD + lane * 4) = acc;

        int f = lane * 4;
        atomicAdd(&ssum[f + 0], acc.x);
        atomicAdd(&ssum[f + 1], acc.y);
        atomicAdd(&ssum[f + 2], acc.z);
        atomicAdd(&ssum[f + 3], acc.w);
        atomicAdd(&ssq[f + 0], acc.x * acc.x);
        atomicAdd(&ssq[f + 1], acc.y * acc.y);
        atomicAdd(&ssq[f + 2], acc.z * acc.z);
        atomicAdd(&ssq[f + 3], acc.w * acc.w);
    }
    __syncthreads();
    if (tid < DD) {
        atomicAdd(&gsum[tid], ssum[tid]);
        atomicAdd(&gsq[tid], ssq[tid]);
    }
}

// ---------------- final aggregation + bias + L2 normalize ----------------
__global__ __launch_bounds__(256) void agg_final_kernel(
    const __half* __restrict__ h, const float* __restrict__ b3,
    float* __restrict__ out)
{
    int gw = (blockIdx.x * blockDim.x + threadIdx.x) >> 5;
    int lane = threadIdx.x & 31;
    if (gw >= NN) return;

    float di = g_dinv[gw];
    float4 acc = make_float4(0.f, 0.f, 0.f, 0.f);
    acc_edge(acc, h, gw, lane, di * di);   // self loop

    int beg = g_rowptr[gw];
    int end = g_rowptr[gw + 1];
    int e = beg;
    for (; e + 3 < end; e += 4) {
        int s0 = g_col[e], s1 = g_col[e + 1], s2 = g_col[e + 2], s3 = g_col[e + 3];
        float w0 = g_w[e], w1 = g_w[e + 1], w2 = g_w[e + 2], w3 = g_w[e + 3];
        acc_edge(acc, h, s0, lane, w0);
        acc_edge(acc, h, s1, lane, w1);
        acc_edge(acc, h, s2, lane, w2);
        acc_edge(acc, h, s3, lane, w3);
    }
    for (; e < end; e++)
        acc_edge(acc, h, g_col[e], lane, g_w[e]);

    float4 bb = ((const float4*)b3)[lane];
    acc.x += bb.x; acc.y += bb.y; acc.z += bb.z; acc.w += bb.w;
    float ss = acc.x * acc.x + acc.y * acc.y + acc.z * acc.z + acc.w * acc.w;
    #pragma unroll
    for (int off = 16; off; off >>= 1)
        ss += __shfl_xor_sync(0xffffffffu, ss, off);
    float inv = 1.0f / fmaxf(sqrtf(ss), 1e-12f);
    float4 o = make_float4(acc.x * inv, acc.y * inv, acc.z * inv, acc.w * inv);
    *(float4*)(out + (size_t)gw * DD + lane * 4) = o;
}

// ---------------- launch ----------------
extern "C" void kernel_launch(void* const* d_in, const int* in_sizes, int n_in,
                              void* d_out, int out_size)
{
    const float* x   = (const float*)d_in[0];
    const int*   ei  = (const int*)d_in[1];
    const float* W1  = (const float*)d_in[2];
    // b1 = d_in[3]  -- no-op before BatchNorm
    const float* W2  = (const float*)d_in[4];
    // b2 = d_in[5]  -- no-op before BatchNorm
    const float* W3  = (const float*)d_in[6];
    const float* b3  = (const float*)d_in[7];
    const float* g1  = (const float*)d_in[8];
    const float* be1 = (const float*)d_in[9];
    const float* g2  = (const float*)d_in[10];
    const float* be2 = (const float*)d_in[11];
    float* out = (float*)d_out;

    __half* d_h;  cudaGetSymbolAddress((void**)&d_h,   g_h);
    float* d_agg; cudaGetSymbolAddress((void**)&d_agg, g_agg);
    __nv_bfloat16* d_wh; cudaGetSymbolAddress((void**)&d_wh, g_wh);
    __nv_bfloat16* d_wl; cudaGetSymbolAddress((void**)&d_wl, g_wl);
    float* d_sum; cudaGetSymbolAddress((void**)&d_sum, g_sum);
    float* d_sq;  cudaGetSymbolAddress((void**)&d_sq,  g_sumsq);
    __nv_bfloat16* wh1 = d_wh,           *wl1 = d_wl;
    __nv_bfloat16* wh2 = d_wh + DD * DD, *wl2 = d_wl + DD * DD;
    __nv_bfloat16* wh3 = d_wh + 2 * DD * DD, *wl3 = d_wl + 2 * DD * DD;
    float* sum0 = d_sum, *sq0 = d_sq;
    float* sum1 = d_sum + DD, *sq1 = d_sq + DD;

    static cudaStream_t sB = nullptr, sC = nullptr;
    static cudaEvent_t e0 = nullptr, eB = nullptr, eC = nullptr;
    if (!sB) {
        cudaStreamCreateWithFlags(&sB, cudaStreamNonBlocking);
        cudaStreamCreateWithFlags(&sC, cudaStreamNonBlocking);
        cudaEventCreateWithFlags(&e0, cudaEventDisableTiming);
        cudaEventCreateWithFlags(&eB, cudaEventDisableTiming);
        cudaEventCreateWithFlags(&eC, cudaEventDisableTiming);
        cudaFuncSetAttribute(gemm_mma_kernel<false>,
                             cudaFuncAttributeMaxDynamicSharedMemorySize, SM_TOTAL);
        cudaFuncSetAttribute(gemm_mma_kernel<true>,
                             cudaFuncAttributeMaxDynamicSharedMemorySize, SM_TOTAL);
    }

    const int GEMM_GRID = (NN + 127) / 128;   // 391
    const int WARP_GRID = NN / 8;             // 6250

    // ---- fork: preprocessing on sB, layer-2/3 weight conversion on sC ----
    cudaEventRecord(e0, 0);
    cudaStreamWaitEvent(sB, e0, 0);
    cudaStreamWaitEvent(sC, e0, 0);

    init_kernel<<<(NN + 255) / 256, 256, 0, sB>>>(ei);
    deg_count_kernel<<<(EE + 255) / 256, 256, 0, sB>>>(ei);
    blocksum_kernel<<<NB, 256, 0, sB>>>();
    scan_bsums_kernel<<<1, 256, 0, sB>>>();
    scatter_scan_kernel<<<NB, 256, 0, sB>>>();
    fill_kernel<<<(EE + 255) / 256, 256, 0, sB>>>(ei);
    cudaEventRecord(eB, sB);

    conv_w_kernel<<<64, 256, 0, sC>>>(W2, wh2, wl2);
    conv_w_kernel<<<64, 256, 0, sC>>>(W3, wh3, wl3);
    cudaEventRecord(eC, sC);

    // ---- main stream: layer 1 GEMM overlaps preprocessing ----
    conv_w_kernel<<<64, 256>>>(W1, wh1, wl1);
    gemm_mma_kernel<false><<<GEMM_GRID, 256, SM_TOTAL>>>(
        x, wh1, wl1, nullptr, nullptr, nullptr, nullptr, d_h);

    cudaStreamWaitEvent(0, eB, 0);   // CSR + stats-zero ready
    agg_stats_kernel<<<WARP_GRID, 256>>>(d_h, d_agg, sum0, sq0);

    // ---- layer 2 (BN params computed in-block from stats buf 0) ----
    cudaStreamWaitEvent(0, eC, 0);   // W2/W3 conversions ready
    gemm_mma_kernel<true><<<GEMM_GRID, 256, SM_TOTAL>>>(
        d_agg, wh2, wl2, g1, be1, sum0, sq0, d_h);
    agg_stats_kernel<<<WARP_GRID, 256>>>(d_h, d_agg, sum1, sq1);

    // ---- layer 3 (BN from stats buf 1; bias + L2norm fused into agg) ----
    gemm_mma_kernel<true><<<GEMM_GRID, 256, SM_TOTAL>>>(
        d_agg, wh3, wl3, g2, be2, sum1, sq1, d_h);
    agg_final_kernel<<<WARP_GRID, 256>>>(d_h, b3, out);
}

// round 14
// speedup vs baseline: 2.4556x; 1.0105x over previous
#include <cuda_runtime.h>
#include <cuda_bf16.h>
#include <cuda_fp16.h>
#include <math.h>
#include <stdint.h>

#define NN 50000
#define EE 800000
#define DD 128
#define BN_EPS 1e-5f
#define NB 196          // ceil(NN/256) scan blocks

// ---------------- device scratch (no allocations allowed) ----------------
__device__ __half g_h[(size_t)NN * DD];   // post-GEMM activations (fp16)
__device__ __half g_agg[(size_t)NN * DD]; // aggregated (fp16)
__device__ __nv_bfloat16 g_wh[3][DD * DD];  // per-layer W^T hi [n][k]
__device__ __nv_bfloat16 g_wl[3][DD * DD];  // per-layer W^T lo [n][k]
__device__ int   g_deg[NN];
__device__ float g_dinv[NN];
__device__ int   g_rowptr[NN + 1];
__device__ int   g_rowcur[NN];
__device__ int   g_col[EE];
__device__ float g_w[EE];                 // per-edge norm weight
__device__ int   g_bsum[256];
__device__ int   g_boff[256];
__device__ float g_sum[2][DD];            // double-buffered BN stats
__device__ float g_sumsq[2][DD];
__device__ int   g_is64;

// ---------------- edge index access (int32 vs int64 tolerant) -----------
__device__ __forceinline__ int edge_src(const int* ei, int e) {
    return g_is64 ? ei[2 * e] : ei[e];
}
__device__ __forceinline__ int edge_dst(const int* ei, int e) {
    return g_is64 ? ei[2 * (EE + e)] : ei[EE + e];
}

// ---------------- graph preprocessing ----------------
__global__ void init_kernel(const int* __restrict__ ei) {
    int i = blockIdx.x * blockDim.x + threadIdx.x;
    if (i < NN) g_deg[i] = 0;
    if (i < DD) {
        g_sum[0][i] = 0.0f; g_sumsq[0][i] = 0.0f;
        g_sum[1][i] = 0.0f; g_sumsq[1][i] = 0.0f;
    }
    if (i == 0) {
        int is64 = 1;
        #pragma unroll
        for (int j = 1; j < 16; j += 2)
            if (ei[j] != 0) is64 = 0;
        g_is64 = is64;
    }
}

__global__ void deg_count_kernel(const int* __restrict__ ei) {
    int e = blockIdx.x * blockDim.x + threadIdx.x;
    if (e < EE) atomicAdd(&g_deg[edge_dst(ei, e)], 1);
}

__global__ __launch_bounds__(256) void blocksum_kernel() {
    int tid = threadIdx.x;
    int i = blockIdx.x * 256 + tid;
    int v = (i < NN) ? g_deg[i] : 0;
    #pragma unroll
    for (int off = 16; off; off >>= 1)
        v += __shfl_xor_sync(0xffffffffu, v, off);
    __shared__ int ws[8];
    if ((tid & 31) == 0) ws[tid >> 5] = v;
    __syncthreads();
    if (tid == 0) {
        int s = 0;
        #pragma unroll
        for (int w = 0; w < 8; w++) s += ws[w];
        g_bsum[blockIdx.x] = s;
    }
}

__global__ __launch_bounds__(256) void scan_bsums_kernel() {
    __shared__ int sm[256];
    int tid = threadIdx.x;
    int v = (tid < NB) ? g_bsum[tid] : 0;
    sm[tid] = v;
    __syncthreads();
    for (int off = 1; off < 256; off <<= 1) {
        int t = (tid >= off) ? sm[tid - off] : 0;
        __syncthreads();
        sm[tid] += t;
        __syncthreads();
    }
    if (tid < NB) g_boff[tid] = sm[tid] - v;       // exclusive
    if (tid == NB - 1) g_rowptr[NN] = sm[tid];     // total
}

__global__ __launch_bounds__(256) void scatter_scan_kernel() {
    __shared__ int sm[256];
    int tid = threadIdx.x;
    int i = blockIdx.x * 256 + tid;
    int d = (i < NN) ? g_deg[i] : 0;
    sm[tid] = d;
    __syncthreads();
    for (int off = 1; off < 256; off <<= 1) {
        int t = (tid >= off) ? sm[tid - off] : 0;
        __syncthreads();
        sm[tid] += t;
        __syncthreads();
    }
    if (i < NN) {
        int pos = g_boff[blockIdx.x] + sm[tid] - d;
        g_rowptr[i] = pos;
        g_rowcur[i] = pos;
        g_dinv[i] = rsqrtf((float)d + 1.0f);       // +1 self loop
    }
}

__global__ void fill_kernel(const int* __restrict__ ei) {
    int e = blockIdx.x * blockDim.x + threadIdx.x;
    if (e < EE) {
        int d = edge_dst(ei, e);
        int s = edge_src(ei, e);
        int pos = atomicAdd(&g_rowcur[d], 1);
        g_col[pos] = s;
        g_w[pos] = g_dinv[s] * g_dinv[d];
    }
}

// W[k][n] -> W^T hi/lo [n][k]
__global__ void conv_w_kernel(const float* __restrict__ W,
                              __nv_bfloat16* __restrict__ wh,
                              __nv_bfloat16* __restrict__ wl)
{
    int i = blockIdx.x * 256 + threadIdx.x;
    if (i >= DD * DD) return;
    int n = i >> 7, k = i & 127;
    float v = W[k * DD + n];
    __nv_bfloat16 h = __float2bfloat16(v);
    __nv_bfloat16 l = __float2bfloat16(v - __bfloat162float(h));
    wh[i] = h;
    wl[i] = l;
}

// ---------------- HMMA GEMM: h[M,128] = act(A)[M,128] @ W[128,128] -----
// mma.sync m16n8k16 bf16 + ldmatrix. Split precision Ah@Wh + Ah@Wl + Al@Wh,
// fp32 accumulate. BN params computed in-block from double-buffered stats;
// BN+ReLU+hi/lo-split fused into A-tile load. A is fp32 for layer 1
// (BN=false), fp16 for layers 2/3 (BN=true, fed by fp16 agg output).
// Output fp16. K in two 64-chunks -> 72KB smem -> occupancy 2.
// CTA tile 128x128, 8 warps = 4(M) x 2(N), each warp 32x64.

#define PITCH 72
#define KC 64
#define TILEB (128 * PITCH * 2)   // 18432
#define SM_AHI 0
#define SM_ALO TILEB
#define SM_WHI (2 * TILEB)
#define SM_WLO (3 * TILEB)
#define SM_TOTAL (4 * TILEB)      // 73728

static __device__ __forceinline__ uint32_t smem_u32(const void* p) {
    uint32_t a;
    asm("{ .reg .u64 t; cvta.to.shared.u64 t, %1; cvt.u32.u64 %0, t; }"
        : "=r"(a) : "l"(p));
    return a;
}

__device__ __forceinline__ void ldm_x4(uint32_t* r, uint32_t addr) {
    asm volatile("ldmatrix.sync.aligned.m8n8.x4.shared.b16 {%0,%1,%2,%3}, [%4];"
                 : "=r"(r[0]), "=r"(r[1]), "=r"(r[2]), "=r"(r[3]) : "r"(addr));
}

__device__ __forceinline__ void mma16816(float* d, const uint32_t* a,
                                         uint32_t b0, uint32_t b1) {
    asm volatile(
        "mma.sync.aligned.m16n8k16.row.col.f32.bf16.bf16.f32 "
        "{%0,%1,%2,%3}, {%4,%5,%6,%7}, {%8,%9}, {%0,%1,%2,%3};"
        : "+f"(d[0]), "+f"(d[1]), "+f"(d[2]), "+f"(d[3])
        : "r"(a[0]), "r"(a[1]), "r"(a[2]), "r"(a[3]), "r"(b0), "r"(b1));
}

template<bool BN>
__global__ __launch_bounds__(256, 2)
void gemm_mma_kernel(const void* __restrict__ Avoid,
                     const __nv_bfloat16* __restrict__ Wh,
                     const __nv_bfloat16* __restrict__ Wl,
                     const float* __restrict__ gamma,
                     const float* __restrict__ beta,
                     const float* __restrict__ gsum,
                     const float* __restrict__ gsq,
                     __half* __restrict__ C)
{
    extern __shared__ char smem[];
    __shared__ float s_scale[DD];
    __shared__ float s_shift[DD];
    uint32_t sbase = smem_u32(smem);
    int tid = threadIdx.x;
    int wid = tid >> 5;
    int lane = tid & 31;
    int m0blk = blockIdx.x * 128;
    int wm = (wid & 3) * 32;        // warp M offset in tile
    int wn = (wid >> 2) * 64;       // warp N offset in tile

    if (BN && tid < DD) {
        float mu = gsum[tid] * (1.0f / NN);
        float var = gsq[tid] * (1.0f / NN) - mu * mu;
        float sc = gamma[tid] * rsqrtf(var + BN_EPS);
        s_scale[tid] = sc;
        s_shift[tid] = beta[tid] - mu * sc;
    }
    if (BN) __syncthreads();

    float acc[2][8][4];
    #pragma unroll
    for (int mt = 0; mt < 2; mt++)
        #pragma unroll
        for (int nt = 0; nt < 8; nt++)
            #pragma unroll
            for (int q = 0; q < 4; q++) acc[mt][nt][q] = 0.0f;

    // ldmatrix lane address components
    int a_row = (lane & 7) + 8 * ((lane >> 3) & 1);
    int a_kof = 8 * (lane >> 4);
    int b_nof = (lane & 7) + 8 * (lane >> 4);
    int b_kof = 8 * ((lane >> 3) & 1);

    #pragma unroll
    for (int kc = 0; kc < 2; kc++) {
        int kbase = kc * KC;
        if (kc) __syncthreads();    // protect previous chunk's tiles

        // A chunk (128 rows x 64 cols) with fused BN+ReLU+split
        for (int idx = tid; idx < 2048; idx += 256) {
            int r = idx >> 4;
            int c4 = (idx & 15) * 4;      // col within chunk
            int gc = kbase + c4;
            float4 v = make_float4(0.f, 0.f, 0.f, 0.f);
            if (m0blk + r < NN) {
                if (BN) {
                    const __half* Ah16 = (const __half*)Avoid;
                    uint2 raw = *(const uint2*)(Ah16 + (size_t)(m0blk + r) * DD + gc);
                    float2 f0 = __half22float2(*(__half2*)&raw.x);
                    float2 f1 = __half22float2(*(__half2*)&raw.y);
                    v = make_float4(f0.x, f0.y, f1.x, f1.y);
                } else {
                    const float* Af = (const float*)Avoid;
                    v = *(const float4*)(Af + (size_t)(m0blk + r) * DD + gc);
                }
            }
            if (BN) {
                v.x = fmaxf(fmaf(v.x, s_scale[gc + 0], s_shift[gc + 0]), 0.0f);
                v.y = fmaxf(fmaf(v.y, s_scale[gc + 1], s_shift[gc + 1]), 0.0f);
                v.z = fmaxf(fmaf(v.z, s_scale[gc + 2], s_shift[gc + 2]), 0.0f);
                v.w = fmaxf(fmaf(v.w, s_scale[gc + 3], s_shift[gc + 3]), 0.0f);
            }
            float a[4] = {v.x, v.y, v.z, v.w};
            uint32_t ph[2], pl[2];
            #pragma unroll
            for (int p = 0; p < 2; p++) {
                __nv_bfloat16 h0 = __float2bfloat16(a[2 * p]);
                __nv_bfloat16 h1 = __float2bfloat16(a[2 * p + 1]);
                __nv_bfloat16 l0 = __float2bfloat16(a[2 * p] - __bfloat162float(h0));
                __nv_bfloat16 l1 = __float2bfloat16(a[2 * p + 1] - __bfloat162float(h1));
                ph[p] = (uint32_t)__bfloat16_as_ushort(h0) | ((uint32_t)__bfloat16_as_ushort(h1) << 16);
                pl[p] = (uint32_t)__bfloat16_as_ushort(l0) | ((uint32_t)__bfloat16_as_ushort(l1) << 16);
            }
            size_t boff = ((size_t)r * PITCH + c4) * 2;
            *(uint2*)(smem + SM_AHI + boff) = make_uint2(ph[0], ph[1]);
            *(uint2*)(smem + SM_ALO + boff) = make_uint2(pl[0], pl[1]);
        }
        // W chunk (128 n-rows x 64 k) hi+lo: 1024 x 16B each
        for (int idx = tid; idx < 1024; idx += 256) {
            int n = idx >> 3;
            int kq = (idx & 7) * 8;
            uint4 vh = *(const uint4*)(Wh + (size_t)n * DD + kbase + kq);
            uint4 vl = *(const uint4*)(Wl + (size_t)n * DD + kbase + kq);
            size_t boff = ((size_t)n * PITCH + kq) * 2;
            *(uint4*)(smem + SM_WHI + boff) = vh;
            *(uint4*)(smem + SM_WLO + boff) = vl;
        }
        __syncthreads();

        #pragma unroll
        for (int k0 = 0; k0 < KC; k0 += 16) {
            uint32_t aH[2][4], aL[2][4];
            #pragma unroll
            for (int mt = 0; mt < 2; mt++) {
                uint32_t ad = sbase + SM_AHI
                    + ((uint32_t)(wm + mt * 16 + a_row) * PITCH + k0 + a_kof) * 2;
                ldm_x4(aH[mt], ad);
                ldm_x4(aL[mt], ad + (SM_ALO - SM_AHI));
            }
            #pragma unroll
            for (int ng = 0; ng < 4; ng++) {
                uint32_t bH[4], bL[4];
                uint32_t bd = sbase + SM_WHI
                    + ((uint32_t)(wn + ng * 16 + b_nof) * PITCH + k0 + b_kof) * 2;
                ldm_x4(bH, bd);
                ldm_x4(bL, bd + (SM_WLO - SM_WHI));
                #pragma unroll
                for (int mt = 0; mt < 2; mt++)
                    #pragma unroll
                    for (int half = 0; half < 2; half++) {
                        int nt = ng * 2 + half;
                        int s = half * 2;
                        mma16816(acc[mt][nt], aH[mt], bH[s], bH[s + 1]);
                        mma16816(acc[mt][nt], aH[mt], bL[s], bL[s + 1]);
                        mma16816(acc[mt][nt], aL[mt], bH[s], bH[s + 1]);
                    }
            }
        }
    }

    // store accumulators as fp16
    #pragma unroll
    for (int mt = 0; mt < 2; mt++) {
        int row0 = m0blk + wm + mt * 16 + (lane >> 2);
        int row1 = row0 + 8;
        #pragma unroll
        for (int nt = 0; nt < 8; nt++) {
            int col = wn + nt * 8 + (lane & 3) * 2;
            if (row0 < NN)
                *(__half2*)(C + (size_t)row0 * DD + col) =
                    __floats2half2_rn(acc[mt][nt][0], acc[mt][nt][1]);
            if (row1 < NN)
                *(__half2*)(C + (size_t)row1 * DD + col) =
                    __floats2half2_rn(acc[mt][nt][2], acc[mt][nt][3]);
        }
    }
}

// ---------------- fp16 gather helper ----------------
__device__ __forceinline__ void acc_edge(float4& acc, const __half* __restrict__ h,
                                         int s, int lane, float w)
{
    uint2 raw = *(const uint2*)(h + (size_t)s * DD + lane * 4);
    float2 f0 = __half22float2(*(__half2*)&raw.x);
    float2 f1 = __half22float2(*(__half2*)&raw.y);
    acc.x = fmaf(f0.x, w, acc.x);
    acc.y = fmaf(f0.y, w, acc.y);
    acc.z = fmaf(f1.x, w, acc.z);
    acc.w = fmaf(f1.y, w, acc.w);
}

// ---------------- aggregation + fused BN statistics (fp16 out) ----------
__global__ __launch_bounds__(256) void agg_stats_kernel(
    const __half* __restrict__ h, __half* __restrict__ out,
    float* __restrict__ gsum, float* __restrict__ gsq)
{
    __shared__ float ssum[DD];
    __shared__ float ssq[DD];
    int tid = threadIdx.x;
    if (tid < DD) { ssum[tid] = 0.0f; ssq[tid] = 0.0f; }
    __syncthreads();

    int gw = (blockIdx.x * blockDim.x + tid) >> 5;
    int lane = tid & 31;

    if (gw < NN) {
        float di = g_dinv[gw];
        float4 acc = make_float4(0.f, 0.f, 0.f, 0.f);
        acc_edge(acc, h, gw, lane, di * di);   // self loop

        int beg = g_rowptr[gw];
        int end = g_rowptr[gw + 1];
        int e = beg;
        for (; e + 3 < end; e += 4) {
            int s0 = g_col[e], s1 = g_col[e + 1], s2 = g_col[e + 2], s3 = g_col[e + 3];
            float w0 = g_w[e], w1 = g_w[e + 1], w2 = g_w[e + 2], w3 = g_w[e + 3];
            acc_edge(acc, h, s0, lane, w0);
            acc_edge(acc, h, s1, lane, w1);
            acc_edge(acc, h, s2, lane, w2);
            acc_edge(acc, h, s3, lane, w3);
        }
        for (; e < end; e++)
            acc_edge(acc, h, g_col[e], lane, g_w[e]);

        // fp16 store (stats stay fp32 from the pre-rounding accumulator)
        uint2 packed;
        *(__half2*)&packed.x = __floats2half2_rn(acc.x, acc.y);
        *(__half2*)&packed.y = __floats2half2_rn(acc.z, acc.w);
        *(uint2*)(out + (size_t)gw * DD + lane * 4) = packed;

        int f = lane * 4;
        atomicAdd(&ssum[f + 0], acc.x);
        atomicAdd(&ssum[f + 1], acc.y);
        atomicAdd(&ssum[f + 2], acc.z);
        atomicAdd(&ssum[f + 3], acc.w);
        atomicAdd(&ssq[f + 0], acc.x * acc.x);
        atomicAdd(&ssq[f + 1], acc.y * acc.y);
        atomicAdd(&ssq[f + 2], acc.z * acc.z);
        atomicAdd(&ssq[f + 3], acc.w * acc.w);
    }
    __syncthreads();
    if (tid < DD) {
        atomicAdd(&gsum[tid], ssum[tid]);
        atomicAdd(&gsq[tid], ssq[tid]);
    }
}

// ---------------- final aggregation + bias + L2 normalize ----------------
__global__ __launch_bounds__(256) void agg_final_kernel(
    const __half* __restrict__ h, const float* __restrict__ b3,
    float* __restrict__ out)
{
    int gw = (blockIdx.x * blockDim.x + threadIdx.x) >> 5;
    int lane = threadIdx.x & 31;
    if (gw >= NN) return;

    float di = g_dinv[gw];
    float4 acc = make_float4(0.f, 0.f, 0.f, 0.f);
    acc_edge(acc, h, gw, lane, di * di);   // self loop

    int beg = g_rowptr[gw];
    int end = g_rowptr[gw + 1];
    int e = beg;
    for (; e + 3 < end; e += 4) {
        int s0 = g_col[e], s1 = g_col[e + 1], s2 = g_col[e + 2], s3 = g_col[e + 3];
        float w0 = g_w[e], w1 = g_w[e + 1], w2 = g_w[e + 2], w3 = g_w[e + 3];
        acc_edge(acc, h, s0, lane, w0);
        acc_edge(acc, h, s1, lane, w1);
        acc_edge(acc, h, s2, lane, w2);
        acc_edge(acc, h, s3, lane, w3);
    }
    for (; e < end; e++)
        acc_edge(acc, h, g_col[e], lane, g_w[e]);

    float4 bb = ((const float4*)b3)[lane];
    acc.x += bb.x; acc.y += bb.y; acc.z += bb.z; acc.w += bb.w;
    float ss = acc.x * acc.x + acc.y * acc.y + acc.z * acc.z + acc.w * acc.w;
    #pragma unroll
    for (int off = 16; off; off >>= 1)
        ss += __shfl_xor_sync(0xffffffffu, ss, off);
    float inv = 1.0f / fmaxf(sqrtf(ss), 1e-12f);
    float4 o = make_float4(acc.x * inv, acc.y * inv, acc.z * inv, acc.w * inv);
    *(float4*)(out + (size_t)gw * DD + lane * 4) = o;
}

// ---------------- launch ----------------
extern "C" void kernel_launch(void* const* d_in, const int* in_sizes, int n_in,
                              void* d_out, int out_size)
{
    const float* x   = (const float*)d_in[0];
    const int*   ei  = (const int*)d_in[1];
    const float* W1  = (const float*)d_in[2];
    // b1 = d_in[3]  -- no-op before BatchNorm
    const float* W2  = (const float*)d_in[4];
    // b2 = d_in[5]  -- no-op before BatchNorm
    const float* W3  = (const float*)d_in[6];
    const float* b3  = (const float*)d_in[7];
    const float* g1  = (const float*)d_in[8];
    const float* be1 = (const float*)d_in[9];
    const float* g2  = (const float*)d_in[10];
    const float* be2 = (const float*)d_in[11];
    float* out = (float*)d_out;

    __half* d_h;   cudaGetSymbolAddress((void**)&d_h,   g_h);
    __half* d_agg; cudaGetSymbolAddress((void**)&d_agg, g_agg);
    __nv_bfloat16* d_wh; cudaGetSymbolAddress((void**)&d_wh, g_wh);
    __nv_bfloat16* d_wl; cudaGetSymbolAddress((void**)&d_wl, g_wl);
    float* d_sum; cudaGetSymbolAddress((void**)&d_sum, g_sum);
    float* d_sq;  cudaGetSymbolAddress((void**)&d_sq,  g_sumsq);
    __nv_bfloat16* wh1 = d_wh,           *wl1 = d_wl;
    __nv_bfloat16* wh2 = d_wh + DD * DD, *wl2 = d_wl + DD * DD;
    __nv_bfloat16* wh3 = d_wh + 2 * DD * DD, *wl3 = d_wl + 2 * DD * DD;
    float* sum0 = d_sum, *sq0 = d_sq;
    float* sum1 = d_sum + DD, *sq1 = d_sq + DD;

    static cudaStream_t sB = nullptr, sC = nullptr;
    static cudaEvent_t e0 = nullptr, eB = nullptr, eC = nullptr;
    if (!sB) {
        cudaStreamCreateWithFlags(&sB, cudaStreamNonBlocking);
        cudaStreamCreateWithFlags(&sC, cudaStreamNonBlocking);
        cudaEventCreateWithFlags(&e0, cudaEventDisableTiming);
        cudaEventCreateWithFlags(&eB, cudaEventDisableTiming);
        cudaEventCreateWithFlags(&eC, cudaEventDisableTiming);
        cudaFuncSetAttribute(gemm_mma_kernel<false>,
                             cudaFuncAttributeMaxDynamicSharedMemorySize, SM_TOTAL);
        cudaFuncSetAttribute(gemm_mma_kernel<true>,
                             cudaFuncAttributeMaxDynamicSharedMemorySize, SM_TOTAL);
    }

    const int GEMM_GRID = (NN + 127) / 128;   // 391
    const int WARP_GRID = NN / 8;             // 6250

    // ---- fork: preprocessing on sB, layer-2/3 weight conversion on sC ----
    cudaEventRecord(e0, 0);
    cudaStreamWaitEvent(sB, e0, 0);
    cudaStreamWaitEvent(sC, e0, 0);

    init_kernel<<<(NN + 255) / 256, 256, 0, sB>>>(ei);
    deg_count_kernel<<<(EE + 255) / 256, 256, 0, sB>>>(ei);
    blocksum_kernel<<<NB, 256, 0, sB>>>();
    scan_bsums_kernel<<<1, 256, 0, sB>>>();
    scatter_scan_kernel<<<NB, 256, 0, sB>>>();
    fill_kernel<<<(EE + 255) / 256, 256, 0, sB>>>(ei);
    cudaEventRecord(eB, sB);

    conv_w_kernel<<<64, 256, 0, sC>>>(W2, wh2, wl2);
    conv_w_kernel<<<64, 256, 0, sC>>>(W3, wh3, wl3);
    cudaEventRecord(eC, sC);

    // ---- main stream: layer 1 GEMM overlaps preprocessing ----
    conv_w_kernel<<<64, 256>>>(W1, wh1, wl1);
    gemm_mma_kernel<false><<<GEMM_GRID, 256, SM_TOTAL>>>(
        x, wh1, wl1, nullptr, nullptr, nullptr, nullptr, d_h);

    cudaStreamWaitEvent(0, eB, 0);   // CSR + stats-zero ready
    agg_stats_kernel<<<WARP_GRID, 256>>>(d_h, d_agg, sum0, sq0);

    // ---- layer 2 (BN params computed in-block from stats buf 0) ----
    cudaStreamWaitEvent(0, eC, 0);   // W2/W3 conversions ready
    gemm_mma_kernel<true><<<GEMM_GRID, 256, SM_TOTAL>>>(
        d_agg, wh2, wl2, g1, be1, sum0, sq0, d_h);
    agg_stats_kernel<<<WARP_GRID, 256>>>(d_h, d_agg, sum1, sq1);

    // ---- layer 3 (BN from stats buf 1; bias + L2norm fused into agg) ----
    gemm_mma_kernel<true><<<GEMM_GRID, 256, SM_TOTAL>>>(
        d_agg, wh3, wl3, g2, be2, sum1, sq1, d_h);
    agg_final_kernel<<<WARP_GRID, 256>>>(d_h, b3, out);
}